// round 2
// baseline (speedup 1.0000x reference)
#include <cuda_runtime.h>
#include <cuda_bf16.h>
#include <math.h>

#define B_  4096
#define T_  256
#define E_  96
#define H_  6
#define HD_ 16
#define V_  98
#define EP  100     // padded row stride for Ek/Ev/Pk/Pv tables (16B-aligned float4 rows)
#define GO  384     // stage-1 fused outputs: [r|z (192) | i_n (96) | h_n (96)]
#define S2O 224     // stage-2 padded outputs: [cand(96) | p(1) | head(98) | pad]
#define BB  8       // batch rows per block in K2
#define RB  32      // batch rows per block in K3

#define K2_SMEM_FLOATS 50504
#define K3_SMEM_FLOATS 23136

// -------- persistent scratch (__device__ globals; no allocation allowed) --------
__device__ float g_Eq[V_*E_];
__device__ float g_Ek[V_*EP];
__device__ float g_Ev[V_*EP];
__device__ float g_Pk[T_*EP];
__device__ float g_Pv[T_*EP];
__device__ float g_pq[E_];
__device__ float g_Gbig[V_*GO];     // per-vocab token contribution + all bias constants
__device__ float g_Wbig[288*GO];    // fused GRU weights; input X = [ctx_raw|memory|hidden]
__device__ float g_W2[E_*S2O];      // fused stage-2 weights [mw^T | pg | (ln_g*head)^T | pad]
__device__ float g_hg[V_];          // sum_e ln_g[e]*head_w[v][e]
__device__ float g_hc1[V_];         // sum_e ln_b[e]*head_w[v][e] + head_b[v]
__device__ float g_ctx[B_*E_];      // raw (pre-out_proj) attention context

// ================================ K1: precompute ================================
__global__ void k1_precompute(
    const float* __restrict__ tok,  const float* __restrict__ pos,
    const float* __restrict__ ipw,  const float* __restrict__ ipb,
    const float* __restrict__ opw,  const float* __restrict__ opb,
    const float* __restrict__ gih,  const float* __restrict__ ghh,
    const float* __restrict__ gbih, const float* __restrict__ gbhh,
    const float* __restrict__ pgw,  const float* __restrict__ mww,
    const float* __restrict__ lng,  const float* __restrict__ lnb,
    const float* __restrict__ headw,const float* __restrict__ headb)
{
    int i = blockIdx.x*blockDim.x + threadIdx.x;

    if (i < V_*E_) {                                    // Eq = tok @ Wq^T
        int v=i/E_, e=i%E_; float s=0.f;
        for (int j=0;j<E_;j++) s += tok[v*E_+j]*ipw[e*E_+j];
        g_Eq[v*E_+e]=s; return;
    }
    i -= V_*E_;
    if (i < V_*E_) {                                    // Ek = tok @ Wk^T
        int v=i/E_, e=i%E_; float s=0.f;
        for (int j=0;j<E_;j++) s += tok[v*E_+j]*ipw[(E_+e)*E_+j];
        g_Ek[v*EP+e]=s; return;
    }
    i -= V_*E_;
    if (i < V_*E_) {                                    // Ev = tok @ Wv^T
        int v=i/E_, e=i%E_; float s=0.f;
        for (int j=0;j<E_;j++) s += tok[v*E_+j]*ipw[(2*E_+e)*E_+j];
        g_Ev[v*EP+e]=s; return;
    }
    i -= V_*E_;
    if (i < T_*E_) {                                    // Pk = pos @ Wk^T + bk
        int t=i/E_, e=i%E_; float s=ipb[E_+e];
        for (int j=0;j<E_;j++) s += pos[t*E_+j]*ipw[(E_+e)*E_+j];
        g_Pk[t*EP+e]=s; return;
    }
    i -= T_*E_;
    if (i < T_*E_) {                                    // Pv = pos @ Wv^T + bv
        int t=i/E_, e=i%E_; float s=ipb[2*E_+e];
        for (int j=0;j<E_;j++) s += pos[t*E_+j]*ipw[(2*E_+e)*E_+j];
        g_Pv[t*EP+e]=s; return;
    }
    i -= T_*E_;
    if (i < E_) {                                       // pq = pos[T-1] @ Wq^T + bq
        int e=i; float s=ipb[e];
        for (int j=0;j<E_;j++) s += pos[(T_-1)*E_+j]*ipw[e*E_+j];
        g_pq[e]=s; return;
    }
    i -= E_;
    if (i < V_*GO) {                                    // Gbig: cur-token + biases
        int v=i/GO, o=i%GO; float s;
        if (o < 288) {
            s = gbih[o];
            for (int j=0;j<E_;j++) s += tok[v*E_+j]*gih[o*288+j];       // cur slot
            if (o < 192) s += gbhh[o];                                   // h_r,h_z bias
            for (int j=0;j<E_;j++) s += gih[o*288+E_+j]*opb[j];          // out_proj bias fold
        } else {
            s = gbhh[192 + (o-288)];                                     // h_n bias
        }
        g_Gbig[v*GO+o]=s; return;
    }
    i -= V_*GO;
    if (i < 288*GO) {                                   // Wbig (out_proj folded)
        int k=i/GO, o=i%GO; float s=0.f;
        if (k < 96) {                       // ctx_raw columns: (W_ih ctx-slice) @ Wo
            if (o < 288) { for (int j=0;j<E_;j++) s += gih[o*288+E_+j]*opw[j*E_+k]; }
        } else if (k < 192) {               // memory columns
            if (o < 288) s = gih[o*288+2*E_+(k-96)];
        } else {                            // hidden columns
            int hh = k-192;
            if (o < 192)       s = ghh[o*E_+hh];
            else if (o >= 288) s = ghh[(192+(o-288))*E_+hh];
        }
        g_Wbig[k*GO+o]=s; return;
    }
    i -= 288*GO;
    if (i < E_*S2O) {                                   // W2
        int e=i/S2O, o=i%S2O; float s=0.f;
        if (o < 96)       s = mww[o*E_+e];
        else if (o == 96) s = pgw[e];
        else if (o < 195) s = headw[(o-97)*E_+e]*lng[e];
        g_W2[e*S2O+o]=s; return;
    }
    i -= E_*S2O;
    if (i < V_) {                                       // hg
        float s=0.f; for (int e=0;e<E_;e++) s += lng[e]*headw[i*E_+e];
        g_hg[i]=s; return;
    }
    i -= V_;
    if (i < V_) {                                       // hc1
        float s=headb[i]; for (int e=0;e<E_;e++) s += lnb[e]*headw[i*E_+e];
        g_hc1[i]=s; return;
    }
}

// ================================ K2: attention ================================
__global__ __launch_bounds__(256) void k2_attn(const int* __restrict__ hist)
{
    extern __shared__ float sm[];
    float* Ek_s = sm;                      // 98*100  = 9800
    float* Pk_s = sm + 9800;               // 256*100 = 25600 -> 35400
    float* qh_s = sm + 35400;              // 8*96    = 768   -> 36168
    float* a_s  = sm + 36168;              // 8*6*256 = 12288 -> 48456
    int*   idx_s= (int*)(sm + 48456);      // 8*256 ints      -> 50504 floats

    const int tid = threadIdx.x;
    const int b0  = blockIdx.x * BB;

    for (int i = tid; i < BB*T_; i += 256)
        idx_s[i] = hist[(b0 + (i>>8))*T_ + (i&255)];
    {
        const float4* s4 = (const float4*)g_Ek; float4* d4 = (float4*)Ek_s;
        for (int i = tid; i < (V_*EP)/4; i += 256) d4[i] = s4[i];
        const float4* s5 = (const float4*)g_Pk; float4* d5 = (float4*)Pk_s;
        for (int i = tid; i < (T_*EP)/4; i += 256) d5[i] = s5[i];
    }
    __syncthreads();

    for (int i = tid; i < BB*E_; i += 256) {            // qh = Eq[last] + pq
        int r = i / E_, e = i % E_;
        int li = idx_s[r*T_ + (T_-1)];
        qh_s[i] = g_Eq[li*E_+e] + g_pq[e];
    }
    __syncthreads();

    {   // scores: thread t owns history position t for all 8 rows
        const int t = tid;
        int myidx[BB];
#pragma unroll
        for (int r=0;r<BB;r++) myidx[r] = idx_s[r*T_+t];
#pragma unroll
        for (int h=0;h<H_;h++){
            const float4* pk4 = (const float4*)(Pk_s + t*EP + h*HD_);
            float4 p0=pk4[0],p1=pk4[1],p2=pk4[2],p3=pk4[3];
#pragma unroll
            for (int r=0;r<BB;r++){
                const float4* q4 = (const float4*)(qh_s + r*E_ + h*HD_);
                const float4* e4 = (const float4*)(Ek_s + myidx[r]*EP + h*HD_);
                float4 q0=q4[0],q1=q4[1],q2=q4[2],q3=q4[3];
                float4 e0=e4[0],e1=e4[1],e2=e4[2],e3=e4[3];
                float s =
                  q0.x*(e0.x+p0.x)+q0.y*(e0.y+p0.y)+q0.z*(e0.z+p0.z)+q0.w*(e0.w+p0.w)
                + q1.x*(e1.x+p1.x)+q1.y*(e1.y+p1.y)+q1.z*(e1.z+p1.z)+q1.w*(e1.w+p1.w)
                + q2.x*(e2.x+p2.x)+q2.y*(e2.y+p2.y)+q2.z*(e2.z+p2.z)+q2.w*(e2.w+p2.w)
                + q3.x*(e3.x+p3.x)+q3.y*(e3.y+p3.y)+q3.z*(e3.z+p3.z)+q3.w*(e3.w+p3.w);
                a_s[(r*H_+h)*T_ + t] = s * 0.25f;
            }
        }
    }
    __syncthreads();

    {   // swap tables to Ev/Pv + warp-per-row softmax (disjoint smem regions)
        const float4* s4 = (const float4*)g_Ev; float4* d4 = (float4*)Ek_s;
        for (int i = tid; i < (V_*EP)/4; i += 256) d4[i] = s4[i];
        const float4* s5 = (const float4*)g_Pv; float4* d5 = (float4*)Pk_s;
        for (int i = tid; i < (T_*EP)/4; i += 256) d5[i] = s5[i];

        int wid = tid>>5, lane = tid&31;
        int r = wid;                        // 8 warps == BB rows
#pragma unroll
        for (int h=0;h<H_;h++){
            float* row = a_s + (r*H_+h)*T_;
            float v[8]; float m = -1e30f;
#pragma unroll
            for (int j=0;j<8;j++){ v[j]=row[lane+32*j]; m = fmaxf(m, v[j]); }
#pragma unroll
            for (int o=16;o;o>>=1) m = fmaxf(m, __shfl_xor_sync(0xffffffffu, m, o));
            float ssum = 0.f;
#pragma unroll
            for (int j=0;j<8;j++){ v[j]=__expf(v[j]-m); ssum += v[j]; }
#pragma unroll
            for (int o=16;o;o>>=1) ssum += __shfl_xor_sync(0xffffffffu, ssum, o);
            float inv = 1.f/ssum;
#pragma unroll
            for (int j=0;j<8;j++) row[lane+32*j] = v[j]*inv;
        }
    }
    __syncthreads();

    if (tid < BB*24) {                      // ctx: thread = (row, 4-wide col group)
        int r = tid/24, g = tid%24;
        int h = g>>2, col = g*4;
        const float* arow = a_s + (r*H_+h)*T_;
        const int*   irow = idx_s + r*T_;
        float ax=0.f, ay=0.f, az=0.f, aw=0.f;
#pragma unroll 4
        for (int t2=0;t2<T_;t2++){
            float av = arow[t2];
            int   ix = irow[t2];
            float4 ev = *(const float4*)(Ek_s + ix*EP + col);   // holds Ev now
            float4 pv = *(const float4*)(Pk_s + t2*EP + col);   // holds Pv now
            ax += av*(ev.x+pv.x); ay += av*(ev.y+pv.y);
            az += av*(ev.z+pv.z); aw += av*(ev.w+pv.w);
        }
        *(float4*)(g_ctx + (b0+r)*E_ + col) = make_float4(ax,ay,az,aw);
    }
}

// ==================== K3: fused GRU + memory gate + LN + head ====================
__global__ __launch_bounds__(256) void k3_gru(
    const int* __restrict__ cidx, const float* __restrict__ hidden,
    const float* __restrict__ memory, const float* __restrict__ mwb,
    const float* __restrict__ pgb,
    float* __restrict__ out_logits, float* __restrict__ out_hidden,
    float* __restrict__ out_memory)
{
    extern __shared__ float sm[];
    float* XsT   = sm;                  // 288*36 = 10368 (k-major, 36-row pad)
    float* Os    = sm + 10368;          // 384*33 = 12672 -> 23040
    float* mu_s  = sm + 23040;          // 32
    float* rs_s  = sm + 23072;          // 32
    int*   cidx_s= (int*)(sm + 23104);  // 32 -> 23136 floats

    const int tid = threadIdx.x;
    const int b0  = blockIdx.x * RB;
    const int wid = tid>>5, lane = tid&31;

    if (tid < RB) cidx_s[tid] = cidx[b0+tid];
    for (int i = tid; i < RB*E_; i += 256){
        int r = i/E_, c = i%E_;
        XsT[c*36 + r]        = g_ctx[(b0+r)*E_ + c];
        XsT[(E_+c)*36 + r]   = memory[(b0+r)*E_ + c];
        XsT[(2*E_+c)*36 + r] = hidden[(b0+r)*E_ + c];
    }
    __syncthreads();

    // stage-1 fused GEMM: Os[o][r] = sum_k X[r][k]*Wbig[k][o] + Gbig[cidx[r]][o]
    for (int tile = wid; tile < 12; tile += 8){
        int o  = tile*32 + lane;
        int k0 = (tile >= 9) ? 192 : 0;
        int k1 = (tile < 6)  ? 288 : ((tile < 9) ? 192 : 288);
        float acc[RB];
#pragma unroll
        for (int r=0;r<RB;r++) acc[r]=0.f;
        for (int k=k0;k<k1;k++){
            float wv = g_Wbig[k*GO + o];
            const float4* xr = (const float4*)(XsT + k*36);
#pragma unroll
            for (int j=0;j<8;j++){
                float4 x = xr[j];
                acc[4*j+0] += x.x*wv; acc[4*j+1] += x.y*wv;
                acc[4*j+2] += x.z*wv; acc[4*j+3] += x.w*wv;
            }
        }
#pragma unroll
        for (int r=0;r<RB;r++) acc[r] += g_Gbig[cidx_s[r]*GO + o];
#pragma unroll
        for (int r=0;r<RB;r++) Os[o*33 + r] = acc[r];
    }
    __syncthreads();

    // GRU elementwise -> new_hidden; stash nh^T in XsT[0:96) (disjoint from the
    // memory region XsT[96*36..) and hidden region XsT[192*36..) still read below)
    for (int i = tid; i < RB*E_; i += 256){
        int r = i/E_, e = i%E_;
        float orv = Os[e*33+r];
        float ozv = Os[(E_+e)*33+r];
        float oin = Os[(2*E_+e)*33+r];
        float ohn = Os[(3*E_+e)*33+r];
        float rr = 1.f/(1.f+__expf(-orv));
        float zz = 1.f/(1.f+__expf(-ozv));
        float nn = tanhf(oin + rr*ohn);
        float hp = XsT[(2*E_+e)*36 + r];
        float nh = (1.f-zz)*nn + zz*hp;
        XsT[e*36 + r] = nh;
        out_hidden[(b0+r)*E_ + e] = nh;
    }
    __syncthreads();

    // per-row mean / rstd (8 threads per row)
    {
        int r = tid>>3, l8 = tid&7;
        float s=0.f, sq=0.f;
        for (int e=l8; e<E_; e+=8){ float v = XsT[e*36+r]; s += v; sq += v*v; }
#pragma unroll
        for (int o=4;o;o>>=1){
            s  += __shfl_xor_sync(0xffffffffu, s,  o);
            sq += __shfl_xor_sync(0xffffffffu, sq, o);
        }
        if (l8==0){
            float mu = s*(1.f/E_);
            float var = sq*(1.f/E_) - mu*mu;
            mu_s[r] = mu;
            rs_s[r] = rsqrtf(var + 1e-5f);
        }
    }
    __syncthreads();

    // stage-2 GEMM: Os[o][r] = sum_e nh[r][e]*W2[e][o]   (o < 224; 7 tiles)
    for (int tile = wid; tile < 7; tile += 8){
        int o = tile*32 + lane;
        float acc[RB];
#pragma unroll
        for (int r=0;r<RB;r++) acc[r]=0.f;
        for (int k=0;k<E_;k++){
            float wv = g_W2[k*S2O + o];
            const float4* xr = (const float4*)(XsT + k*36);
#pragma unroll
            for (int j=0;j<8;j++){
                float4 x = xr[j];
                acc[4*j+0] += x.x*wv; acc[4*j+1] += x.y*wv;
                acc[4*j+2] += x.z*wv; acc[4*j+3] += x.w*wv;
            }
        }
#pragma unroll
        for (int r=0;r<RB;r++) Os[o*33 + r] = acc[r];
    }
    __syncthreads();

    // epilogue: memory gate
    float pgb0 = pgb[0];
    for (int i = tid; i < RB*E_; i += 256){
        int r = i/E_, e = i%E_;
        float p    = 1.f/(1.f+__expf(-(Os[96*33+r] + pgb0)));
        float cand = tanhf(Os[e*33+r] + mwb[e]);
        float mem  = XsT[(E_+e)*36 + r];
        out_memory[(b0+r)*E_ + e] = (1.f-p)*mem + p*cand;
    }
    // epilogue: logits via folded LN+head
    for (int i = tid; i < RB*V_; i += 256){
        int r = i/V_, v = i%V_;
        float y = Os[(97+v)*33 + r];
        out_logits[(b0+r)*V_ + v] = rs_s[r]*(y - mu_s[r]*g_hg[v]) + g_hc1[v];
    }
}

// ================================== launch ==================================
extern "C" void kernel_launch(void* const* d_in, const int* in_sizes, int n_in,
                              void* d_out, int out_size)
{
    const int*   cidx = (const int*)  d_in[0];
    const int*   hist = (const int*)  d_in[1];
    const float* hid  = (const float*)d_in[2];
    const float* mem  = (const float*)d_in[3];
    const float* tok  = (const float*)d_in[4];
    const float* pos  = (const float*)d_in[5];
    const float* ipw  = (const float*)d_in[6];
    const float* ipb  = (const float*)d_in[7];
    const float* opw  = (const float*)d_in[8];
    const float* opb  = (const float*)d_in[9];
    const float* gih  = (const float*)d_in[10];
    const float* ghh  = (const float*)d_in[11];
    const float* gbih = (const float*)d_in[12];
    const float* gbhh = (const float*)d_in[13];
    const float* pgw  = (const float*)d_in[14];
    const float* pgb  = (const float*)d_in[15];
    const float* mww  = (const float*)d_in[16];
    const float* mwb  = (const float*)d_in[17];
    const float* lng  = (const float*)d_in[18];
    const float* lnb  = (const float*)d_in[19];
    const float* hdw  = (const float*)d_in[20];
    const float* hdb  = (const float*)d_in[21];

    float* out         = (float*)d_out;
    float* out_logits  = out;
    float* out_hidden  = out + (size_t)B_*V_;
    float* out_memory  = out + (size_t)B_*V_ + (size_t)B_*E_;

    cudaFuncSetAttribute(k2_attn, cudaFuncAttributeMaxDynamicSharedMemorySize,
                         K2_SMEM_FLOATS*4);
    cudaFuncSetAttribute(k3_gru,  cudaFuncAttributeMaxDynamicSharedMemorySize,
                         K3_SMEM_FLOATS*4);

    const int k1_total = 3*V_*E_ + 2*T_*E_ + E_ + V_*GO + 288*GO + E_*S2O + 2*V_;
    k1_precompute<<<(k1_total+255)/256, 256>>>(tok,pos,ipw,ipb,opw,opb,
                                               gih,ghh,gbih,gbhh,pgw,mww,
                                               lng,lnb,hdw,hdb);
    k2_attn<<<B_/BB, 256, K2_SMEM_FLOATS*4>>>(hist);
    k3_gru <<<B_/RB, 256, K3_SMEM_FLOATS*4>>>(cidx, hid, mem, mwb, pgb,
                                              out_logits, out_hidden, out_memory);
}

// round 3
// speedup vs baseline: 1.2322x; 1.2322x over previous
#include <cuda_runtime.h>
#include <cuda_bf16.h>
#include <math.h>

#define B_  4096
#define T_  256
#define E_  96
#define H_  6
#define HD_ 16
#define V_  98
#define EP  100     // padded row stride for Ek/Ev/Pk/Pv tables (16B-aligned float4 rows)
#define GO  384     // stage-1 fused outputs: [r|z (192) | i_n (96) | h_n (96)]
#define S2O 224     // stage-2 padded outputs: [cand(96) | p(1) | head(98) | pad]
#define BB  8       // batch rows per block in K2
#define RB  32      // batch rows per block in K3

#define K2_SMEM_FLOATS 50504
#define K3_SMEM_FLOATS 23136

// -------- persistent scratch (__device__ globals; no allocation allowed) --------
__device__ float g_Eq[V_*E_];
__device__ float g_Ek[V_*EP];
__device__ float g_Ev[V_*EP];
__device__ float g_Pk[T_*EP];
__device__ float g_Pv[T_*EP];
__device__ float g_pq[E_];
__device__ float g_Gbig[V_*GO];     // per-vocab token contribution + all bias constants
__device__ float g_Wbig[288*GO];    // fused GRU weights; input X = [ctx_raw|memory|hidden]
__device__ float g_W2[E_*S2O];      // fused stage-2 weights [mw^T | pg | (ln_g*head)^T | pad]
__device__ float g_hg[V_];          // sum_e ln_g[e]*head_w[v][e]
__device__ float g_hc1[V_];         // sum_e ln_b[e]*head_w[v][e] + head_b[v]
__device__ float g_ctx[B_*E_];      // raw (pre-out_proj) attention context

__device__ __forceinline__ float dot4(float4 a, float4 b, float s){
    s = fmaf(a.x, b.x, s); s = fmaf(a.y, b.y, s);
    s = fmaf(a.z, b.z, s); s = fmaf(a.w, b.w, s);
    return s;
}

// ================================ K1: precompute ================================
// All inner products use float4 (LDG.128). Lane-strided operands touch 16B/lane
// per instruction and consecutive j-iters of the same thread consume the rest of
// each 128B line from L1 — fixes the 4B-per-line pathology seen in R2 ncu.
__global__ void k1_precompute(
    const float* __restrict__ tok,  const float* __restrict__ pos,
    const float* __restrict__ ipw,  const float* __restrict__ ipb,
    const float* __restrict__ opw,  const float* __restrict__ opb,
    const float* __restrict__ gih,  const float* __restrict__ ghh,
    const float* __restrict__ gbih, const float* __restrict__ gbhh,
    const float* __restrict__ pgw,  const float* __restrict__ mww,
    const float* __restrict__ lng,  const float* __restrict__ lnb,
    const float* __restrict__ headw,const float* __restrict__ headb)
{
    int i = blockIdx.x*blockDim.x + threadIdx.x;

    if (i < V_*E_) {                                    // Eq = tok @ Wq^T
        int v=i/E_, e=i%E_; float s=0.f;
        const float4* a4 = (const float4*)(tok + v*E_);
        const float4* b4 = (const float4*)(ipw + e*E_);
#pragma unroll 6
        for (int j=0;j<E_/4;j++) s = dot4(a4[j], b4[j], s);
        g_Eq[v*E_+e]=s; return;
    }
    i -= V_*E_;
    if (i < V_*E_) {                                    // Ek = tok @ Wk^T
        int v=i/E_, e=i%E_; float s=0.f;
        const float4* a4 = (const float4*)(tok + v*E_);
        const float4* b4 = (const float4*)(ipw + (E_+e)*E_);
#pragma unroll 6
        for (int j=0;j<E_/4;j++) s = dot4(a4[j], b4[j], s);
        g_Ek[v*EP+e]=s; return;
    }
    i -= V_*E_;
    if (i < V_*E_) {                                    // Ev = tok @ Wv^T
        int v=i/E_, e=i%E_; float s=0.f;
        const float4* a4 = (const float4*)(tok + v*E_);
        const float4* b4 = (const float4*)(ipw + (2*E_+e)*E_);
#pragma unroll 6
        for (int j=0;j<E_/4;j++) s = dot4(a4[j], b4[j], s);
        g_Ev[v*EP+e]=s; return;
    }
    i -= V_*E_;
    if (i < T_*E_) {                                    // Pk = pos @ Wk^T + bk
        int t=i/E_, e=i%E_; float s=ipb[E_+e];
        const float4* a4 = (const float4*)(pos + t*E_);
        const float4* b4 = (const float4*)(ipw + (E_+e)*E_);
#pragma unroll 6
        for (int j=0;j<E_/4;j++) s = dot4(a4[j], b4[j], s);
        g_Pk[t*EP+e]=s; return;
    }
    i -= T_*E_;
    if (i < T_*E_) {                                    // Pv = pos @ Wv^T + bv
        int t=i/E_, e=i%E_; float s=ipb[2*E_+e];
        const float4* a4 = (const float4*)(pos + t*E_);
        const float4* b4 = (const float4*)(ipw + (2*E_+e)*E_);
#pragma unroll 6
        for (int j=0;j<E_/4;j++) s = dot4(a4[j], b4[j], s);
        g_Pv[t*EP+e]=s; return;
    }
    i -= T_*E_;
    if (i < E_) {                                       // pq = pos[T-1] @ Wq^T + bq
        int e=i; float s=ipb[e];
        const float4* a4 = (const float4*)(pos + (T_-1)*E_);
        const float4* b4 = (const float4*)(ipw + e*E_);
#pragma unroll 6
        for (int j=0;j<E_/4;j++) s = dot4(a4[j], b4[j], s);
        g_pq[e]=s; return;
    }
    i -= E_;
    if (i < V_*GO) {                                    // Gbig: cur-token + biases
        int v=i/GO, o=i%GO; float s;
        if (o < 288) {
            s = gbih[o];
            if (o < 192) s += gbhh[o];
            const float4* a4 = (const float4*)(tok + v*E_);
            const float4* b4 = (const float4*)(gih + o*288);        // cur slot j<96
#pragma unroll 6
            for (int j=0;j<E_/4;j++) s = dot4(a4[j], b4[j], s);
            const float4* c4 = (const float4*)opb;
            const float4* d4 = (const float4*)(gih + o*288 + E_);   // out_proj bias fold
#pragma unroll 6
            for (int j=0;j<E_/4;j++) s = dot4(c4[j], d4[j], s);
        } else {
            s = gbhh[192 + (o-288)];
        }
        g_Gbig[v*GO+o]=s; return;
    }
    i -= V_*GO;
    if (i < 288*GO) {                                   // Wbig (out_proj folded)
        int k=i/GO, o=i%GO; float s=0.f;
        if (k < 96) {                       // ctx_raw columns: (W_ih ctx-slice) @ Wo
            if (o < 288) {
                const float4* g4 = (const float4*)(gih + o*288 + E_);
#pragma unroll 4
                for (int j4=0;j4<E_/4;j4++){
                    float4 g = g4[j4];
                    int j = 4*j4;
                    // opw[j][k]: same address for all lanes (o varies, k fixed) -> broadcast
                    s = fmaf(g.x, opw[(j+0)*E_+k], s);
                    s = fmaf(g.y, opw[(j+1)*E_+k], s);
                    s = fmaf(g.z, opw[(j+2)*E_+k], s);
                    s = fmaf(g.w, opw[(j+3)*E_+k], s);
                }
            }
        } else if (k < 192) {               // memory columns
            if (o < 288) s = gih[o*288+2*E_+(k-96)];
        } else {                            // hidden columns
            int hh = k-192;
            if (o < 192)       s = ghh[o*E_+hh];
            else if (o >= 288) s = ghh[(192+(o-288))*E_+hh];
        }
        g_Wbig[k*GO+o]=s; return;
    }
    i -= 288*GO;
    if (i < E_*S2O) {                                   // W2
        int e=i/S2O, o=i%S2O; float s=0.f;
        if (o < 96)       s = mww[o*E_+e];
        else if (o == 96) s = pgw[e];
        else if (o < 195) s = headw[(o-97)*E_+e]*lng[e];
        g_W2[e*S2O+o]=s; return;
    }
    i -= E_*S2O;
    if (i < V_) {                                       // hg
        float s=0.f;
        const float4* a4 = (const float4*)lng;
        const float4* b4 = (const float4*)(headw + i*E_);
#pragma unroll 6
        for (int j=0;j<E_/4;j++) s = dot4(a4[j], b4[j], s);
        g_hg[i]=s; return;
    }
    i -= V_;
    if (i < V_) {                                       // hc1
        float s=headb[i];
        const float4* a4 = (const float4*)lnb;
        const float4* b4 = (const float4*)(headw + i*E_);
#pragma unroll 6
        for (int j=0;j<E_/4;j++) s = dot4(a4[j], b4[j], s);
        g_hc1[i]=s; return;
    }
}

// ================================ K2: attention ================================
__global__ __launch_bounds__(256) void k2_attn(const int* __restrict__ hist)
{
    extern __shared__ float sm[];
    float* Ek_s = sm;                      // 98*100  = 9800
    float* Pk_s = sm + 9800;               // 256*100 = 25600 -> 35400
    float* qh_s = sm + 35400;              // 8*96    = 768   -> 36168
    float* a_s  = sm + 36168;              // 8*6*256 = 12288 -> 48456
    int*   idx_s= (int*)(sm + 48456);      // 8*256 ints      -> 50504 floats

    const int tid = threadIdx.x;
    const int b0  = blockIdx.x * BB;

    for (int i = tid; i < BB*T_; i += 256)
        idx_s[i] = hist[(b0 + (i>>8))*T_ + (i&255)];
    {
        const float4* s4 = (const float4*)g_Ek; float4* d4 = (float4*)Ek_s;
        for (int i = tid; i < (V_*EP)/4; i += 256) d4[i] = s4[i];
        const float4* s5 = (const float4*)g_Pk; float4* d5 = (float4*)Pk_s;
        for (int i = tid; i < (T_*EP)/4; i += 256) d5[i] = s5[i];
    }
    __syncthreads();

    for (int i = tid; i < BB*E_; i += 256) {            // qh = Eq[last] + pq
        int r = i / E_, e = i % E_;
        int li = idx_s[r*T_ + (T_-1)];
        qh_s[i] = g_Eq[li*E_+e] + g_pq[e];
    }
    __syncthreads();

    {   // scores: thread t owns history position t for all 8 rows
        const int t = tid;
        int myidx[BB];
#pragma unroll
        for (int r=0;r<BB;r++) myidx[r] = idx_s[r*T_+t];
#pragma unroll
        for (int h=0;h<H_;h++){
            const float4* pk4 = (const float4*)(Pk_s + t*EP + h*HD_);
            float4 p0=pk4[0],p1=pk4[1],p2=pk4[2],p3=pk4[3];
#pragma unroll
            for (int r=0;r<BB;r++){
                const float4* q4 = (const float4*)(qh_s + r*E_ + h*HD_);
                const float4* e4 = (const float4*)(Ek_s + myidx[r]*EP + h*HD_);
                float4 q0=q4[0],q1=q4[1],q2=q4[2],q3=q4[3];
                float4 e0=e4[0],e1=e4[1],e2=e4[2],e3=e4[3];
                float s =
                  q0.x*(e0.x+p0.x)+q0.y*(e0.y+p0.y)+q0.z*(e0.z+p0.z)+q0.w*(e0.w+p0.w)
                + q1.x*(e1.x+p1.x)+q1.y*(e1.y+p1.y)+q1.z*(e1.z+p1.z)+q1.w*(e1.w+p1.w)
                + q2.x*(e2.x+p2.x)+q2.y*(e2.y+p2.y)+q2.z*(e2.z+p2.z)+q2.w*(e2.w+p2.w)
                + q3.x*(e3.x+p3.x)+q3.y*(e3.y+p3.y)+q3.z*(e3.z+p3.z)+q3.w*(e3.w+p3.w);
                a_s[(r*H_+h)*T_ + t] = s * 0.25f;
            }
        }
    }
    __syncthreads();

    {   // swap tables to Ev/Pv + warp-per-row softmax (disjoint smem regions)
        const float4* s4 = (const float4*)g_Ev; float4* d4 = (float4*)Ek_s;
        for (int i = tid; i < (V_*EP)/4; i += 256) d4[i] = s4[i];
        const float4* s5 = (const float4*)g_Pv; float4* d5 = (float4*)Pk_s;
        for (int i = tid; i < (T_*EP)/4; i += 256) d5[i] = s5[i];

        int wid = tid>>5, lane = tid&31;
        int r = wid;                        // 8 warps == BB rows
#pragma unroll
        for (int h=0;h<H_;h++){
            float* row = a_s + (r*H_+h)*T_;
            float v[8]; float m = -1e30f;
#pragma unroll
            for (int j=0;j<8;j++){ v[j]=row[lane+32*j]; m = fmaxf(m, v[j]); }
#pragma unroll
            for (int o=16;o;o>>=1) m = fmaxf(m, __shfl_xor_sync(0xffffffffu, m, o));
            float ssum = 0.f;
#pragma unroll
            for (int j=0;j<8;j++){ v[j]=__expf(v[j]-m); ssum += v[j]; }
#pragma unroll
            for (int o=16;o;o>>=1) ssum += __shfl_xor_sync(0xffffffffu, ssum, o);
            float inv = 1.f/ssum;
#pragma unroll
            for (int j=0;j<8;j++) row[lane+32*j] = v[j]*inv;
        }
    }
    __syncthreads();

    if (tid < BB*24) {                      // ctx: thread = (row, 4-wide col group)
        int r = tid/24, g = tid%24;
        int h = g>>2, col = g*4;
        const float* arow = a_s + (r*H_+h)*T_;
        const int*   irow = idx_s + r*T_;
        float ax=0.f, ay=0.f, az=0.f, aw=0.f;
#pragma unroll 4
        for (int t2=0;t2<T_;t2++){
            float av = arow[t2];
            int   ix = irow[t2];
            float4 ev = *(const float4*)(Ek_s + ix*EP + col);   // holds Ev now
            float4 pv = *(const float4*)(Pk_s + t2*EP + col);   // holds Pv now
            ax += av*(ev.x+pv.x); ay += av*(ev.y+pv.y);
            az += av*(ev.z+pv.z); aw += av*(ev.w+pv.w);
        }
        *(float4*)(g_ctx + (b0+r)*E_ + col) = make_float4(ax,ay,az,aw);
    }
}

// ==================== K3: fused GRU + memory gate + LN + head ====================
__global__ __launch_bounds__(256) void k3_gru(
    const int* __restrict__ cidx, const float* __restrict__ hidden,
    const float* __restrict__ memory, const float* __restrict__ mwb,
    const float* __restrict__ pgb,
    float* __restrict__ out_logits, float* __restrict__ out_hidden,
    float* __restrict__ out_memory)
{
    extern __shared__ float sm[];
    float* XsT   = sm;                  // 288*36 = 10368 (k-major, 36-row pad)
    float* Os    = sm + 10368;          // 384*33 = 12672 -> 23040
    float* mu_s  = sm + 23040;          // 32
    float* rs_s  = sm + 23072;          // 32
    int*   cidx_s= (int*)(sm + 23104);  // 32 -> 23136 floats

    const int tid = threadIdx.x;
    const int b0  = blockIdx.x * RB;
    const int wid = tid>>5, lane = tid&31;

    if (tid < RB) cidx_s[tid] = cidx[b0+tid];
    for (int i = tid; i < RB*E_; i += 256){
        int r = i/E_, c = i%E_;
        XsT[c*36 + r]        = g_ctx[(b0+r)*E_ + c];
        XsT[(E_+c)*36 + r]   = memory[(b0+r)*E_ + c];
        XsT[(2*E_+c)*36 + r] = hidden[(b0+r)*E_ + c];
    }
    __syncthreads();

    // stage-1 fused GEMM: Os[o][r] = sum_k X[r][k]*Wbig[k][o] + Gbig[cidx[r]][o]
    for (int tile = wid; tile < 12; tile += 8){
        int o  = tile*32 + lane;
        int k0 = (tile >= 9) ? 192 : 0;
        int k1 = (tile < 6)  ? 288 : ((tile < 9) ? 192 : 288);
        float acc[RB];
#pragma unroll
        for (int r=0;r<RB;r++) acc[r]=0.f;
        for (int k=k0;k<k1;k++){
            float wv = g_Wbig[k*GO + o];
            const float4* xr = (const float4*)(XsT + k*36);
#pragma unroll
            for (int j=0;j<8;j++){
                float4 x = xr[j];
                acc[4*j+0] += x.x*wv; acc[4*j+1] += x.y*wv;
                acc[4*j+2] += x.z*wv; acc[4*j+3] += x.w*wv;
            }
        }
#pragma unroll
        for (int r=0;r<RB;r++) acc[r] += g_Gbig[cidx_s[r]*GO + o];
#pragma unroll
        for (int r=0;r<RB;r++) Os[o*33 + r] = acc[r];
    }
    __syncthreads();

    // GRU elementwise -> new_hidden; stash nh^T in XsT[0:96)
    for (int i = tid; i < RB*E_; i += 256){
        int r = i/E_, e = i%E_;
        float orv = Os[e*33+r];
        float ozv = Os[(E_+e)*33+r];
        float oin = Os[(2*E_+e)*33+r];
        float ohn = Os[(3*E_+e)*33+r];
        float rr = 1.f/(1.f+__expf(-orv));
        float zz = 1.f/(1.f+__expf(-ozv));
        float nn = tanhf(oin + rr*ohn);
        float hp = XsT[(2*E_+e)*36 + r];
        float nh = (1.f-zz)*nn + zz*hp;
        XsT[e*36 + r] = nh;
        out_hidden[(b0+r)*E_ + e] = nh;
    }
    __syncthreads();

    // per-row mean / rstd (8 threads per row)
    {
        int r = tid>>3, l8 = tid&7;
        float s=0.f, sq=0.f;
        for (int e=l8; e<E_; e+=8){ float v = XsT[e*36+r]; s += v; sq += v*v; }
#pragma unroll
        for (int o=4;o;o>>=1){
            s  += __shfl_xor_sync(0xffffffffu, s,  o);
            sq += __shfl_xor_sync(0xffffffffu, sq, o);
        }
        if (l8==0){
            float mu = s*(1.f/E_);
            float var = sq*(1.f/E_) - mu*mu;
            mu_s[r] = mu;
            rs_s[r] = rsqrtf(var + 1e-5f);
        }
    }
    __syncthreads();

    // stage-2 GEMM: Os[o][r] = sum_e nh[r][e]*W2[e][o]   (o < 224; 7 tiles)
    for (int tile = wid; tile < 7; tile += 8){
        int o = tile*32 + lane;
        float acc[RB];
#pragma unroll
        for (int r=0;r<RB;r++) acc[r]=0.f;
        for (int k=0;k<E_;k++){
            float wv = g_W2[k*S2O + o];
            const float4* xr = (const float4*)(XsT + k*36);
#pragma unroll
            for (int j=0;j<8;j++){
                float4 x = xr[j];
                acc[4*j+0] += x.x*wv; acc[4*j+1] += x.y*wv;
                acc[4*j+2] += x.z*wv; acc[4*j+3] += x.w*wv;
            }
        }
#pragma unroll
        for (int r=0;r<RB;r++) Os[o*33 + r] = acc[r];
    }
    __syncthreads();

    // epilogue: memory gate
    float pgb0 = pgb[0];
    for (int i = tid; i < RB*E_; i += 256){
        int r = i/E_, e = i%E_;
        float p    = 1.f/(1.f+__expf(-(Os[96*33+r] + pgb0)));
        float cand = tanhf(Os[e*33+r] + mwb[e]);
        float mem  = XsT[(E_+e)*36 + r];
        out_memory[(b0+r)*E_ + e] = (1.f-p)*mem + p*cand;
    }
    // epilogue: logits via folded LN+head
    for (int i = tid; i < RB*V_; i += 256){
        int r = i/V_, v = i%V_;
        float y = Os[(97+v)*33 + r];
        out_logits[(b0+r)*V_ + v] = rs_s[r]*(y - mu_s[r]*g_hg[v]) + g_hc1[v];
    }
}

// ================================== launch ==================================
extern "C" void kernel_launch(void* const* d_in, const int* in_sizes, int n_in,
                              void* d_out, int out_size)
{
    const int*   cidx = (const int*)  d_in[0];
    const int*   hist = (const int*)  d_in[1];
    const float* hid  = (const float*)d_in[2];
    const float* mem  = (const float*)d_in[3];
    const float* tok  = (const float*)d_in[4];
    const float* pos  = (const float*)d_in[5];
    const float* ipw  = (const float*)d_in[6];
    const float* ipb  = (const float*)d_in[7];
    const float* opw  = (const float*)d_in[8];
    const float* opb  = (const float*)d_in[9];
    const float* gih  = (const float*)d_in[10];
    const float* ghh  = (const float*)d_in[11];
    const float* gbih = (const float*)d_in[12];
    const float* gbhh = (const float*)d_in[13];
    const float* pgw  = (const float*)d_in[14];
    const float* pgb  = (const float*)d_in[15];
    const float* mww  = (const float*)d_in[16];
    const float* mwb  = (const float*)d_in[17];
    const float* lng  = (const float*)d_in[18];
    const float* lnb  = (const float*)d_in[19];
    const float* hdw  = (const float*)d_in[20];
    const float* hdb  = (const float*)d_in[21];

    float* out         = (float*)d_out;
    float* out_logits  = out;
    float* out_hidden  = out + (size_t)B_*V_;
    float* out_memory  = out + (size_t)B_*V_ + (size_t)B_*E_;

    cudaFuncSetAttribute(k2_attn, cudaFuncAttributeMaxDynamicSharedMemorySize,
                         K2_SMEM_FLOATS*4);
    cudaFuncSetAttribute(k3_gru,  cudaFuncAttributeMaxDynamicSharedMemorySize,
                         K3_SMEM_FLOATS*4);

    const int k1_total = 3*V_*E_ + 2*T_*E_ + E_ + V_*GO + 288*GO + E_*S2O + 2*V_;
    k1_precompute<<<(k1_total+255)/256, 256>>>(tok,pos,ipw,ipb,opw,opb,
                                               gih,ghh,gbih,gbhh,pgw,mww,
                                               lng,lnb,hdw,hdb);
    k2_attn<<<B_/BB, 256, K2_SMEM_FLOATS*4>>>(hist);
    k3_gru <<<B_/RB, 256, K3_SMEM_FLOATS*4>>>(cidx, hid, mem, mwb, pgb,
                                              out_logits, out_hidden, out_memory);
}

// round 5
// speedup vs baseline: 1.3821x; 1.1217x over previous
#include <cuda_runtime.h>
#include <cuda_fp16.h>
#include <cuda_bf16.h>
#include <math.h>

#define B_  4096
#define T_  256
#define E_  96
#define H_  6
#define HD_ 16
#define V_  98
#define EP  100     // padded row stride (halves) for Ek/Ev/Pk/Pv tables
#define GO  384     // stage-1 fused outputs: [r|z (192) | i_n (96) | h_n (96)]
#define S2O 224     // stage-2 padded outputs: [cand(96) | p(1) | head(98) | pad]
#define BB  8       // batch rows per block in K2
#define RB  32      // batch rows per block in K3

#define K2_SMEM_BYTES 102544
#define K3_SMEM_FLOATS 23136

// -------- persistent scratch (__device__ globals; no allocation allowed) --------
__device__ float g_Eq[V_*E_];
__device__ __align__(16) __half g_Ek[V_*EP];
__device__ __align__(16) __half g_Ev[V_*EP];
__device__ __align__(16) __half g_Pk[T_*EP];
__device__ __align__(16) __half g_Pv[T_*EP];
__device__ float g_pq[E_];
__device__ float g_Gbig[V_*GO];     // per-vocab token contribution + all bias constants
__device__ float g_Wbig[288*GO];    // fused GRU weights; input X = [ctx_raw|memory|hidden]
__device__ float g_W2[E_*S2O];      // fused stage-2 weights [mw^T | pg | (ln_g*head)^T | pad]
__device__ float g_hg[V_];          // sum_e ln_g[e]*head_w[v][e]
__device__ float g_hc1[V_];         // sum_e ln_b[e]*head_w[v][e] + head_b[v]
__device__ float g_ctx[B_*E_];      // raw (pre-out_proj) attention context

__device__ __forceinline__ float dot4(float4 a, float4 b, float s){
    s = fmaf(a.x, b.x, s); s = fmaf(a.y, b.y, s);
    s = fmaf(a.z, b.z, s); s = fmaf(a.w, b.w, s);
    return s;
}
__device__ __forceinline__ float2 h2f(unsigned int u){
    return __half22float2(*reinterpret_cast<const __half2*>(&u));
}
// packed fp32x2 FMA (Blackwell): d = a*b + d, bit-exact IEEE fp32 per lane half
#define FMA2(d,a,b) asm("fma.rn.f32x2 %0, %1, %2, %0;" : "+l"(d) : "l"(a), "l"(b))

// ================================ K1: precompute ================================
__global__ void k1_precompute(
    const float* __restrict__ tok,  const float* __restrict__ pos,
    const float* __restrict__ ipw,  const float* __restrict__ ipb,
    const float* __restrict__ opw,  const float* __restrict__ opb,
    const float* __restrict__ gih,  const float* __restrict__ ghh,
    const float* __restrict__ gbih, const float* __restrict__ gbhh,
    const float* __restrict__ pgw,  const float* __restrict__ mww,
    const float* __restrict__ lng,  const float* __restrict__ lnb,
    const float* __restrict__ headw,const float* __restrict__ headb)
{
    int i = blockIdx.x*blockDim.x + threadIdx.x;

    if (i < V_*E_) {                                    // Eq = tok @ Wq^T (fp32)
        int v=i/E_, e=i%E_; float s=0.f;
        const float4* a4 = (const float4*)(tok + v*E_);
        const float4* b4 = (const float4*)(ipw + e*E_);
#pragma unroll 6
        for (int j=0;j<E_/4;j++) s = dot4(a4[j], b4[j], s);
        g_Eq[v*E_+e]=s; return;
    }
    i -= V_*E_;
    if (i < V_*E_) {                                    // Ek = tok @ Wk^T (fp16)
        int v=i/E_, e=i%E_; float s=0.f;
        const float4* a4 = (const float4*)(tok + v*E_);
        const float4* b4 = (const float4*)(ipw + (E_+e)*E_);
#pragma unroll 6
        for (int j=0;j<E_/4;j++) s = dot4(a4[j], b4[j], s);
        g_Ek[v*EP+e]=__float2half(s); return;
    }
    i -= V_*E_;
    if (i < V_*E_) {                                    // Ev = tok @ Wv^T (fp16)
        int v=i/E_, e=i%E_; float s=0.f;
        const float4* a4 = (const float4*)(tok + v*E_);
        const float4* b4 = (const float4*)(ipw + (2*E_+e)*E_);
#pragma unroll 6
        for (int j=0;j<E_/4;j++) s = dot4(a4[j], b4[j], s);
        g_Ev[v*EP+e]=__float2half(s); return;
    }
    i -= V_*E_;
    if (i < T_*E_) {                                    // Pk = pos @ Wk^T + bk (fp16)
        int t=i/E_, e=i%E_; float s=ipb[E_+e];
        const float4* a4 = (const float4*)(pos + t*E_);
        const float4* b4 = (const float4*)(ipw + (E_+e)*E_);
#pragma unroll 6
        for (int j=0;j<E_/4;j++) s = dot4(a4[j], b4[j], s);
        g_Pk[t*EP+e]=__float2half(s); return;
    }
    i -= T_*E_;
    if (i < T_*E_) {                                    // Pv = pos @ Wv^T + bv (fp16)
        int t=i/E_, e=i%E_; float s=ipb[2*E_+e];
        const float4* a4 = (const float4*)(pos + t*E_);
        const float4* b4 = (const float4*)(ipw + (2*E_+e)*E_);
#pragma unroll 6
        for (int j=0;j<E_/4;j++) s = dot4(a4[j], b4[j], s);
        g_Pv[t*EP+e]=__float2half(s); return;
    }
    i -= T_*E_;
    if (i < E_) {                                       // pq = pos[T-1] @ Wq^T + bq
        int e=i; float s=ipb[e];
        const float4* a4 = (const float4*)(pos + (T_-1)*E_);
        const float4* b4 = (const float4*)(ipw + e*E_);
#pragma unroll 6
        for (int j=0;j<E_/4;j++) s = dot4(a4[j], b4[j], s);
        g_pq[e]=s; return;
    }
    i -= E_;
    if (i < V_*GO) {                                    // Gbig: cur-token + biases
        int v=i/GO, o=i%GO; float s;
        if (o < 288) {
            s = gbih[o];
            if (o < 192) s += gbhh[o];
            const float4* a4 = (const float4*)(tok + v*E_);
            const float4* b4 = (const float4*)(gih + o*288);
#pragma unroll 6
            for (int j=0;j<E_/4;j++) s = dot4(a4[j], b4[j], s);
            const float4* c4 = (const float4*)opb;
            const float4* d4 = (const float4*)(gih + o*288 + E_);
#pragma unroll 6
            for (int j=0;j<E_/4;j++) s = dot4(c4[j], d4[j], s);
        } else {
            s = gbhh[192 + (o-288)];
        }
        g_Gbig[v*GO+o]=s; return;
    }
    i -= V_*GO;
    if (i < 288*GO) {                                   // Wbig (out_proj folded)
        int k=i/GO, o=i%GO; float s=0.f;
        if (k < 96) {
            if (o < 288) {
                const float4* g4 = (const float4*)(gih + o*288 + E_);
#pragma unroll 4
                for (int j4=0;j4<E_/4;j4++){
                    float4 g = g4[j4];
                    int j = 4*j4;
                    s = fmaf(g.x, opw[(j+0)*E_+k], s);
                    s = fmaf(g.y, opw[(j+1)*E_+k], s);
                    s = fmaf(g.z, opw[(j+2)*E_+k], s);
                    s = fmaf(g.w, opw[(j+3)*E_+k], s);
                }
            }
        } else if (k < 192) {
            if (o < 288) s = gih[o*288+2*E_+(k-96)];
        } else {
            int hh = k-192;
            if (o < 192)       s = ghh[o*E_+hh];
            else if (o >= 288) s = ghh[(192+(o-288))*E_+hh];
        }
        g_Wbig[k*GO+o]=s; return;
    }
    i -= 288*GO;
    if (i < E_*S2O) {                                   // W2
        int e=i/S2O, o=i%S2O; float s=0.f;
        if (o < 96)       s = mww[o*E_+e];
        else if (o == 96) s = pgw[e];
        else if (o < 195) s = headw[(o-97)*E_+e]*lng[e];
        g_W2[e*S2O+o]=s; return;
    }
    i -= E_*S2O;
    if (i < V_) {                                       // hg
        float s=0.f;
        const float4* a4 = (const float4*)lng;
        const float4* b4 = (const float4*)(headw + i*E_);
#pragma unroll 6
        for (int j=0;j<E_/4;j++) s = dot4(a4[j], b4[j], s);
        g_hg[i]=s; return;
    }
    i -= V_;
    if (i < V_) {                                       // hc1
        float s=headb[i];
        const float4* a4 = (const float4*)lnb;
        const float4* b4 = (const float4*)(headw + i*E_);
#pragma unroll 6
        for (int j=0;j<E_/4;j++) s = dot4(a4[j], b4[j], s);
        g_hc1[i]=s; return;
    }
}

// ================================ K2: attention (fp16 tables) ================================
// smem: Ek 19600 B | Pk 51200 B | qh 3072 B | a 24576 B | idx 4096 B = 102544 B -> 2 CTAs/SM
__global__ __launch_bounds__(256) void k2_attn(const int* __restrict__ hist)
{
    extern __shared__ char smc[];
    __half* Ek_s = (__half*)smc;                            // 9800 halves
    __half* Pk_s = (__half*)(smc + 19600);                  // 25600 halves
    float*  qh_s = (float*)(smc + 70800);                   // 768 floats
    __half* a_s  = (__half*)(smc + 73872);                  // 12288 halves
    unsigned short* idx_s = (unsigned short*)(smc + 98448); // 2048 u16

    const int tid = threadIdx.x;
    const int b0  = blockIdx.x * BB;

    for (int i = tid; i < BB*T_; i += 256)
        idx_s[i] = (unsigned short)hist[(b0 + (i>>8))*T_ + (i&255)];
    {   // stage Ek, Pk (fp16, uint4 = 8 halves)
        const uint4* s4 = (const uint4*)g_Ek; uint4* d4 = (uint4*)Ek_s;
        for (int i = tid; i < (V_*EP)/8; i += 256) d4[i] = s4[i];
        const uint4* s5 = (const uint4*)g_Pk; uint4* d5 = (uint4*)Pk_s;
        for (int i = tid; i < (T_*EP)/8; i += 256) d5[i] = s5[i];
    }
    __syncthreads();

    for (int i = tid; i < BB*E_; i += 256) {            // qh = Eq[last] + pq (fp32)
        int r = i / E_, e = i % E_;
        int li = idx_s[r*T_ + (T_-1)];
        qh_s[i] = g_Eq[li*E_+e] + g_pq[e];
    }
    __syncthreads();

    {   // scores: thread t owns history position t for all 8 rows
        const int t = tid;
        int myidx[BB];
#pragma unroll
        for (int r=0;r<BB;r++) myidx[r] = idx_s[r*T_+t];
#pragma unroll
        for (int h=0;h<H_;h++){
            const uint2* pk2 = (const uint2*)(Pk_s + t*EP + h*HD_);
            uint2 pu0=pk2[0], pu1=pk2[1], pu2=pk2[2], pu3=pk2[3];
            float2 p0=h2f(pu0.x),p1=h2f(pu0.y),p2=h2f(pu1.x),p3=h2f(pu1.y);
            float2 p4=h2f(pu2.x),p5=h2f(pu2.y),p6=h2f(pu3.x),p7=h2f(pu3.y);
#pragma unroll
            for (int r=0;r<BB;r++){
                const float4* q4 = (const float4*)(qh_s + r*E_ + h*HD_);
                float4 q0=q4[0],q1=q4[1],q2=q4[2],q3=q4[3];
                const uint2* e2 = (const uint2*)(Ek_s + myidx[r]*EP + h*HD_);
                uint2 u0=e2[0],u1=e2[1],u2=e2[2],u3=e2[3];
                float2 e0=h2f(u0.x),e1=h2f(u0.y),e2f_=h2f(u1.x),e3=h2f(u1.y);
                float2 e4=h2f(u2.x),e5=h2f(u2.y),e6=h2f(u3.x),e7=h2f(u3.y);
                float s =
                  q0.x*(e0.x+p0.x)+q0.y*(e0.y+p0.y)+q0.z*(e1.x+p1.x)+q0.w*(e1.y+p1.y)
                + q1.x*(e2f_.x+p2.x)+q1.y*(e2f_.y+p2.y)+q1.z*(e3.x+p3.x)+q1.w*(e3.y+p3.y)
                + q2.x*(e4.x+p4.x)+q2.y*(e4.y+p4.y)+q2.z*(e5.x+p5.x)+q2.w*(e5.y+p5.y)
                + q3.x*(e6.x+p6.x)+q3.y*(e6.y+p6.y)+q3.z*(e7.x+p7.x)+q3.w*(e7.y+p7.y);
                a_s[(r*H_+h)*T_ + t] = __float2half(s * 0.25f);
            }
        }
    }
    __syncthreads();

    {   // swap tables to Ev/Pv + warp-per-row softmax (disjoint smem regions)
        const uint4* s4 = (const uint4*)g_Ev; uint4* d4 = (uint4*)Ek_s;
        for (int i = tid; i < (V_*EP)/8; i += 256) d4[i] = s4[i];
        const uint4* s5 = (const uint4*)g_Pv; uint4* d5 = (uint4*)Pk_s;
        for (int i = tid; i < (T_*EP)/8; i += 256) d5[i] = s5[i];

        int wid = tid>>5, lane = tid&31;
        int r = wid;
#pragma unroll
        for (int h=0;h<H_;h++){
            __half* row = a_s + (r*H_+h)*T_;
            float v[8]; float m = -1e30f;
#pragma unroll
            for (int j=0;j<8;j++){ v[j]=__half2float(row[lane+32*j]); m = fmaxf(m, v[j]); }
#pragma unroll
            for (int o=16;o;o>>=1) m = fmaxf(m, __shfl_xor_sync(0xffffffffu, m, o));
            float ssum = 0.f;
#pragma unroll
            for (int j=0;j<8;j++){ v[j]=__expf(v[j]-m); ssum += v[j]; }
#pragma unroll
            for (int o=16;o;o>>=1) ssum += __shfl_xor_sync(0xffffffffu, ssum, o);
            float inv = 1.f/ssum;
#pragma unroll
            for (int j=0;j<8;j++) row[lane+32*j] = __float2half(v[j]*inv);
        }
    }
    __syncthreads();

    if (tid < BB*24) {                      // ctx: thread = (row, 4-wide col group)
        int r = tid/24, g = tid%24;
        int h = g>>2, col = g*4;
        const __half* arow = a_s + (r*H_+h)*T_;
        const unsigned short* irow = idx_s + r*T_;
        float ax=0.f, ay=0.f, az=0.f, aw=0.f;
#pragma unroll 4
        for (int t2=0;t2<T_;t2++){
            float av = __half2float(arow[t2]);
            int   ix = irow[t2];
            uint2 eu = *(const uint2*)(Ek_s + ix*EP + col);   // holds Ev now
            uint2 pu = *(const uint2*)(Pk_s + t2*EP + col);   // holds Pv now
            float2 e0=h2f(eu.x), e1=h2f(eu.y), p0=h2f(pu.x), p1=h2f(pu.y);
            ax += av*(e0.x+p0.x); ay += av*(e0.y+p0.y);
            az += av*(e1.x+p1.x); aw += av*(e1.y+p1.y);
        }
        *(float4*)(g_ctx + (b0+r)*E_ + col) = make_float4(ax,ay,az,aw);
    }
}

// ==================== K3: fused GRU + memory gate + LN + head ====================
__global__ __launch_bounds__(256) void k3_gru(
    const int* __restrict__ cidx, const float* __restrict__ hidden,
    const float* __restrict__ memory, const float* __restrict__ mwb,
    const float* __restrict__ pgb,
    float* __restrict__ out_logits, float* __restrict__ out_hidden,
    float* __restrict__ out_memory)
{
    extern __shared__ float sm[];
    float* XsT   = sm;                  // 288*36 = 10368 (k-major, 36-row pad)
    float* Os    = sm + 10368;          // 384*33 = 12672 -> 23040
    float* mu_s  = sm + 23040;          // 32
    float* rs_s  = sm + 23072;          // 32
    int*   cidx_s= (int*)(sm + 23104);  // 32 -> 23136 floats

    const int tid = threadIdx.x;
    const int b0  = blockIdx.x * RB;
    const int wid = tid>>5, lane = tid&31;

    if (tid < RB) cidx_s[tid] = cidx[b0+tid];
    for (int i = tid; i < RB*E_; i += 256){
        int r = i/E_, c = i%E_;
        XsT[c*36 + r]        = g_ctx[(b0+r)*E_ + c];
        XsT[(E_+c)*36 + r]   = memory[(b0+r)*E_ + c];
        XsT[(2*E_+c)*36 + r] = hidden[(b0+r)*E_ + c];
    }
    __syncthreads();

    // stage-1 fused GEMM with packed f32x2 FMA:
    // Os[o][r] = sum_k X[r][k]*Wbig[k][o] + Gbig[cidx[r]][o]
    for (int tile = wid; tile < 12; tile += 8){
        int o  = tile*32 + lane;
        int k0 = (tile >= 9) ? 192 : 0;
        int k1 = (tile < 6)  ? 288 : ((tile < 9) ? 192 : 288);
        unsigned long long acc2[16];
#pragma unroll
        for (int j=0;j<16;j++) acc2[j]=0ull;
#pragma unroll 4
        for (int k=k0;k<k1;k++){
            float wv = g_Wbig[k*GO + o];
            unsigned long long wv2;
            asm("mov.b64 %0, {%1, %1};" : "=l"(wv2) : "f"(wv));
            const ulonglong2* xr = (const ulonglong2*)(XsT + k*36);
#pragma unroll
            for (int j=0;j<8;j++){
                ulonglong2 x = xr[j];           // 4 floats = 2 packed f32x2
                FMA2(acc2[2*j],   x.x, wv2);
                FMA2(acc2[2*j+1], x.y, wv2);
            }
        }
        const float* gb = g_Gbig;               // unpack + bias + store
#pragma unroll
        for (int j=0;j<16;j++){
            float lo, hi;
            asm("mov.b64 {%0, %1}, %2;" : "=f"(lo), "=f"(hi) : "l"(acc2[j]));
            int r0 = 2*j, r1 = 2*j+1;
            Os[o*33 + r0] = lo + gb[cidx_s[r0]*GO + o];
            Os[o*33 + r1] = hi + gb[cidx_s[r1]*GO + o];
        }
    }
    __syncthreads();

    // GRU elementwise -> new_hidden; stash nh^T in XsT[0:96)
    for (int i = tid; i < RB*E_; i += 256){
        int r = i/E_, e = i%E_;
        float orv = Os[e*33+r];
        float ozv = Os[(E_+e)*33+r];
        float oin = Os[(2*E_+e)*33+r];
        float ohn = Os[(3*E_+e)*33+r];
        float rr = 1.f/(1.f+__expf(-orv));
        float zz = 1.f/(1.f+__expf(-ozv));
        float nn = tanhf(oin + rr*ohn);
        float hp = XsT[(2*E_+e)*36 + r];
        float nh = (1.f-zz)*nn + zz*hp;
        XsT[e*36 + r] = nh;
        out_hidden[(b0+r)*E_ + e] = nh;
    }
    __syncthreads();

    // per-row mean / rstd (8 threads per row)
    {
        int r = tid>>3, l8 = tid&7;
        float s=0.f, sq=0.f;
        for (int e=l8; e<E_; e+=8){ float v = XsT[e*36+r]; s += v; sq += v*v; }
#pragma unroll
        for (int o=4;o;o>>=1){
            s  += __shfl_xor_sync(0xffffffffu, s,  o);
            sq += __shfl_xor_sync(0xffffffffu, sq, o);
        }
        if (l8==0){
            float mu = s*(1.f/E_);
            float var = sq*(1.f/E_) - mu*mu;
            mu_s[r] = mu;
            rs_s[r] = rsqrtf(var + 1e-5f);
        }
    }
    __syncthreads();

    // stage-2 GEMM (packed f32x2): Os[o][r] = sum_e nh[r][e]*W2[e][o]
    for (int tile = wid; tile < 7; tile += 8){
        int o = tile*32 + lane;
        unsigned long long acc2[16];
#pragma unroll
        for (int j=0;j<16;j++) acc2[j]=0ull;
#pragma unroll 4
        for (int k=0;k<E_;k++){
            float wv = g_W2[k*S2O + o];
            unsigned long long wv2;
            asm("mov.b64 %0, {%1, %1};" : "=l"(wv2) : "f"(wv));
            const ulonglong2* xr = (const ulonglong2*)(XsT + k*36);
#pragma unroll
            for (int j=0;j<8;j++){
                ulonglong2 x = xr[j];
                FMA2(acc2[2*j],   x.x, wv2);
                FMA2(acc2[2*j+1], x.y, wv2);
            }
        }
#pragma unroll
        for (int j=0;j<16;j++){
            float lo, hi;
            asm("mov.b64 {%0, %1}, %2;" : "=f"(lo), "=f"(hi) : "l"(acc2[j]));
            Os[o*33 + 2*j]   = lo;
            Os[o*33 + 2*j+1] = hi;
        }
    }
    __syncthreads();

    // epilogue: memory gate
    float pgb0 = pgb[0];
    for (int i = tid; i < RB*E_; i += 256){
        int r = i/E_, e = i%E_;
        float p    = 1.f/(1.f+__expf(-(Os[96*33+r] + pgb0)));
        float cand = tanhf(Os[e*33+r] + mwb[e]);
        float mem  = XsT[(E_+e)*36 + r];
        out_memory[(b0+r)*E_ + e] = (1.f-p)*mem + p*cand;
    }
    // epilogue: logits via folded LN+head
    for (int i = tid; i < RB*V_; i += 256){
        int r = i/V_, v = i%V_;
        float y = Os[(97+v)*33 + r];
        out_logits[(b0+r)*V_ + v] = rs_s[r]*(y - mu_s[r]*g_hg[v]) + g_hc1[v];
    }
}

// ================================== launch ==================================
extern "C" void kernel_launch(void* const* d_in, const int* in_sizes, int n_in,
                              void* d_out, int out_size)
{
    const int*   cidx = (const int*)  d_in[0];
    const int*   hist = (const int*)  d_in[1];
    const float* hid  = (const float*)d_in[2];
    const float* mem  = (const float*)d_in[3];
    const float* tok  = (const float*)d_in[4];
    const float* pos  = (const float*)d_in[5];
    const float* ipw  = (const float*)d_in[6];
    const float* ipb  = (const float*)d_in[7];
    const float* opw  = (const float*)d_in[8];
    const float* opb  = (const float*)d_in[9];
    const float* gih  = (const float*)d_in[10];
    const float* ghh  = (const float*)d_in[11];
    const float* gbih = (const float*)d_in[12];
    const float* gbhh = (const float*)d_in[13];
    const float* pgw  = (const float*)d_in[14];
    const float* pgb  = (const float*)d_in[15];
    const float* mww  = (const float*)d_in[16];
    const float* mwb  = (const float*)d_in[17];
    const float* lng  = (const float*)d_in[18];
    const float* lnb  = (const float*)d_in[19];
    const float* hdw  = (const float*)d_in[20];
    const float* hdb  = (const float*)d_in[21];

    float* out         = (float*)d_out;
    float* out_logits  = out;
    float* out_hidden  = out + (size_t)B_*V_;
    float* out_memory  = out + (size_t)B_*V_ + (size_t)B_*E_;

    cudaFuncSetAttribute(k2_attn, cudaFuncAttributeMaxDynamicSharedMemorySize,
                         K2_SMEM_BYTES);
    cudaFuncSetAttribute(k3_gru,  cudaFuncAttributeMaxDynamicSharedMemorySize,
                         K3_SMEM_FLOATS*4);

    const int k1_total = 3*V_*E_ + 2*T_*E_ + E_ + V_*GO + 288*GO + E_*S2O + 2*V_;
    k1_precompute<<<(k1_total+255)/256, 256>>>(tok,pos,ipw,ipb,opw,opb,
                                               gih,ghh,gbih,gbhh,pgw,mww,
                                               lng,lnb,hdw,hdb);
    k2_attn<<<B_/BB, 256, K2_SMEM_BYTES>>>(hist);
    k3_gru <<<B_/RB, 256, K3_SMEM_FLOATS*4>>>(cidx, hid, mem, mwb, pgb,
                                              out_logits, out_hidden, out_memory);
}

// round 8
// speedup vs baseline: 1.5761x; 1.1404x over previous
#include <cuda_runtime.h>
#include <cuda_fp16.h>
#include <cuda_bf16.h>
#include <math.h>

#define B_  4096
#define T_  256
#define E_  96
#define H_  6
#define HD_ 16
#define V_  98
#define EP  100     // padded row stride (halves) for Ek/Ev/Pk/Pv tables
#define GO  384     // stage-1 fused outputs: [r|z (192) | i_n (96) | h_n (96)]
#define S2O 224     // stage-2 padded outputs: [cand(96) | p(1) | head(98) | pad]
#define BB  8       // batch rows per block in K2
#define RB  32      // batch rows per block in K3

#define K2_SMEM_BYTES 111952
#define K3_SMEM_FLOATS 23136

// -------- persistent scratch (__device__ globals; no allocation allowed) --------
__device__ float g_Eq[V_*E_];
__device__ __align__(16) __half g_Ek[V_*EP];
__device__ __align__(16) __half g_Ev[V_*EP];
__device__ __align__(16) __half g_Pk[T_*EP];
__device__ __align__(16) __half g_Pv[T_*EP];
__device__ float g_pq[E_];
__device__ float g_Gbig[V_*GO];     // per-vocab token contribution + all bias constants
__device__ float g_Wbig[288*GO];    // fused GRU weights; input X = [ctx_raw|memory|hidden]
__device__ float g_W2[E_*S2O];      // fused stage-2 weights [mw^T | pg | (ln_g*head)^T | pad]
__device__ float g_hg[V_];          // sum_e ln_g[e]*head_w[v][e]
__device__ float g_hc1[V_];         // sum_e ln_b[e]*head_w[v][e] + head_b[v]
__device__ float g_ctx[B_*E_];      // raw (pre-out_proj) attention context

__device__ __forceinline__ float dot4(float4 a, float4 b, float s){
    s = fmaf(a.x, b.x, s); s = fmaf(a.y, b.y, s);
    s = fmaf(a.z, b.z, s); s = fmaf(a.w, b.w, s);
    return s;
}
// 96-elem dot with 4 independent accumulator chains (breaks FMA latency chain)
__device__ __forceinline__ float dot96(const float4* a4, const float4* b4, float s){
    float s0=s, s1=0.f, s2=0.f, s3=0.f;
#pragma unroll
    for (int j=0;j<24;j+=4){
        s0 = dot4(a4[j+0], b4[j+0], s0);
        s1 = dot4(a4[j+1], b4[j+1], s1);
        s2 = dot4(a4[j+2], b4[j+2], s2);
        s3 = dot4(a4[j+3], b4[j+3], s3);
    }
    return (s0+s1)+(s2+s3);
}
__device__ __forceinline__ float2 h2f(unsigned int u){
    return __half22float2(*reinterpret_cast<const __half2*>(&u));
}
// packed fp32x2 FMA (Blackwell): d = a*b + d, bit-exact IEEE fp32 per lane half
#define FMA2(d,a,b) asm("fma.rn.f32x2 %0, %1, %2, %0;" : "+l"(d) : "l"(a), "l"(b))

// ================================ K1: precompute ================================
__global__ void k1_precompute(
    const float* __restrict__ tok,  const float* __restrict__ pos,
    const float* __restrict__ ipw,  const float* __restrict__ ipb,
    const float* __restrict__ opw,  const float* __restrict__ opb,
    const float* __restrict__ gih,  const float* __restrict__ ghh,
    const float* __restrict__ gbih, const float* __restrict__ gbhh,
    const float* __restrict__ pgw,  const float* __restrict__ mww,
    const float* __restrict__ lng,  const float* __restrict__ lnb,
    const float* __restrict__ headw,const float* __restrict__ headb)
{
    int i = blockIdx.x*blockDim.x + threadIdx.x;

    if (i < V_*E_) {                                    // Eq = tok @ Wq^T (fp32)
        int v=i/E_, e=i%E_;
        g_Eq[v*E_+e] = dot96((const float4*)(tok + v*E_), (const float4*)(ipw + e*E_), 0.f);
        return;
    }
    i -= V_*E_;
    if (i < V_*E_) {                                    // Ek = tok @ Wk^T (fp16)
        int v=i/E_, e=i%E_;
        float s = dot96((const float4*)(tok + v*E_), (const float4*)(ipw + (E_+e)*E_), 0.f);
        g_Ek[v*EP+e]=__float2half(s); return;
    }
    i -= V_*E_;
    if (i < V_*E_) {                                    // Ev = tok @ Wv^T (fp16)
        int v=i/E_, e=i%E_;
        float s = dot96((const float4*)(tok + v*E_), (const float4*)(ipw + (2*E_+e)*E_), 0.f);
        g_Ev[v*EP+e]=__float2half(s); return;
    }
    i -= V_*E_;
    if (i < T_*E_) {                                    // Pk = pos @ Wk^T + bk (fp16)
        int t=i/E_, e=i%E_;
        float s = dot96((const float4*)(pos + t*E_), (const float4*)(ipw + (E_+e)*E_), ipb[E_+e]);
        g_Pk[t*EP+e]=__float2half(s); return;
    }
    i -= T_*E_;
    if (i < T_*E_) {                                    // Pv = pos @ Wv^T + bv (fp16)
        int t=i/E_, e=i%E_;
        float s = dot96((const float4*)(pos + t*E_), (const float4*)(ipw + (2*E_+e)*E_), ipb[2*E_+e]);
        g_Pv[t*EP+e]=__float2half(s); return;
    }
    i -= T_*E_;
    if (i < E_) {                                       // pq = pos[T-1] @ Wq^T + bq
        int e=i;
        g_pq[e] = dot96((const float4*)(pos + (T_-1)*E_), (const float4*)(ipw + e*E_), ipb[e]);
        return;
    }
    i -= E_;
    if (i < V_*GO) {                                    // Gbig: cur-token + biases
        int v=i/GO, o=i%GO; float s;
        if (o < 288) {
            s = gbih[o];
            if (o < 192) s += gbhh[o];
            s = dot96((const float4*)(tok + v*E_), (const float4*)(gih + o*288), s);
            s = dot96((const float4*)opb, (const float4*)(gih + o*288 + E_), s);
        } else {
            s = gbhh[192 + (o-288)];
        }
        g_Gbig[v*GO+o]=s; return;
    }
    i -= V_*GO;
    if (i < 288*GO) {                                   // Wbig (out_proj folded)
        int k=i/GO, o=i%GO; float s=0.f;
        if (k < 96) {
            if (o < 288) {
                const float4* g4 = (const float4*)(gih + o*288 + E_);
                float s1=0.f;
#pragma unroll 4
                for (int j4=0;j4<E_/4;j4++){
                    float4 g = g4[j4];
                    int j = 4*j4;
                    s  = fmaf(g.x, opw[(j+0)*E_+k], s);
                    s1 = fmaf(g.y, opw[(j+1)*E_+k], s1);
                    s  = fmaf(g.z, opw[(j+2)*E_+k], s);
                    s1 = fmaf(g.w, opw[(j+3)*E_+k], s1);
                }
                s += s1;
            }
        } else if (k < 192) {
            if (o < 288) s = gih[o*288+2*E_+(k-96)];
        } else {
            int hh = k-192;
            if (o < 192)       s = ghh[o*E_+hh];
            else if (o >= 288) s = ghh[(192+(o-288))*E_+hh];
        }
        g_Wbig[k*GO+o]=s; return;
    }
    i -= 288*GO;
    if (i < E_*S2O) {                                   // W2
        int e=i/S2O, o=i%S2O; float s=0.f;
        if (o < 96)       s = mww[o*E_+e];
        else if (o == 96) s = pgw[e];
        else if (o < 195) s = headw[(o-97)*E_+e]*lng[e];
        g_W2[e*S2O+o]=s; return;
    }
    i -= E_*S2O;
    if (i < V_) {                                       // hg
        g_hg[i] = dot96((const float4*)lng, (const float4*)(headw + i*E_), 0.f);
        return;
    }
    i -= V_;
    if (i < V_) {                                       // hc1
        g_hc1[i] = dot96((const float4*)lnb, (const float4*)(headw + i*E_), headb[i]);
        return;
    }
}

// ================================ K2: attention ================================
// smem: Ek 19600 | Pk 51200 | qh 3072 | a 24576 | idx 4096 | SE 9408+pad = 111952 B
// -> 2 CTAs/SM.  SE[r,h,v] = 0.25*q[r,h]·Ek[v] precomputed per block removes all
// scattered Ek gathers + 16 FADD/(h,r) + cvts from the hot score loop.
__global__ __launch_bounds__(256) void k2_attn(const int* __restrict__ hist)
{
    extern __shared__ char smc[];
    __half* Ek_s = (__half*)smc;                            // 9800 halves
    __half* Pk_s = (__half*)(smc + 19600);                  // 25600 halves
    float*  qh_s = (float*)(smc + 70800);                   // 768 floats
    __half* a_s  = (__half*)(smc + 73872);                  // 12288 halves
    unsigned short* idx_s = (unsigned short*)(smc + 98448); // 2048 u16
    __half* SE_s = (__half*)(smc + 102544);                 // 48*98 = 4704 halves

    const int tid = threadIdx.x;
    const int b0  = blockIdx.x * BB;

    for (int i = tid; i < BB*T_; i += 256)
        idx_s[i] = (unsigned short)hist[(b0 + (i>>8))*T_ + (i&255)];
    {   // stage Ek, Pk (fp16, uint4 = 8 halves)
        const uint4* s4 = (const uint4*)g_Ek; uint4* d4 = (uint4*)Ek_s;
        for (int i = tid; i < (V_*EP)/8; i += 256) d4[i] = s4[i];
        const uint4* s5 = (const uint4*)g_Pk; uint4* d5 = (uint4*)Pk_s;
        for (int i = tid; i < (T_*EP)/8; i += 256) d5[i] = s5[i];
    }
    __syncthreads();

    for (int i = tid; i < BB*E_; i += 256) {            // qh = Eq[last] + pq (fp32)
        int r = i / E_, e = i % E_;
        int li = idx_s[r*T_ + (T_-1)];
        qh_s[i] = g_Eq[li*E_+e] + g_pq[e];
    }
    __syncthreads();

    // SE phase: SE[r,h,v] = 0.25 * q[r,h] · Ek[v]   (588 items, ~2.3/thread)
    for (int i = tid; i < H_*V_; i += 256){
        int h = i / V_, v = i % V_;
        const uint2* e2 = (const uint2*)(Ek_s + v*EP + h*HD_);
        uint2 u0=e2[0],u1=e2[1],u2=e2[2],u3=e2[3];
        float2 e0=h2f(u0.x),e1=h2f(u0.y),e2f_=h2f(u1.x),e3=h2f(u1.y);
        float2 e4=h2f(u2.x),e5=h2f(u2.y),e6=h2f(u3.x),e7=h2f(u3.y);
#pragma unroll
        for (int r=0;r<BB;r++){
            const float4* q4 = (const float4*)(qh_s + r*E_ + h*HD_);
            float4 q0=q4[0],q1=q4[1],q2=q4[2],q3=q4[3];
            float s =
              q0.x*e0.x+q0.y*e0.y+q0.z*e1.x+q0.w*e1.y
            + q1.x*e2f_.x+q1.y*e2f_.y+q1.z*e3.x+q1.w*e3.y
            + q2.x*e4.x+q2.y*e4.y+q2.z*e5.x+q2.w*e5.y
            + q3.x*e6.x+q3.y*e6.y+q3.z*e7.x+q3.w*e7.y;
            SE_s[(r*H_+h)*V_ + v] = __float2half(s * 0.25f);
        }
    }
    __syncthreads();

    {   // score phase: thread t owns position t; score = SE[r,h,idx] + 0.25*q·Pk[t]
        const int t = tid;
        int myidx[BB];
#pragma unroll
        for (int r=0;r<BB;r++) myidx[r] = idx_s[r*T_+t];
#pragma unroll
        for (int h=0;h<H_;h++){
            const uint2* pk2 = (const uint2*)(Pk_s + t*EP + h*HD_);
            uint2 pu0=pk2[0], pu1=pk2[1], pu2=pk2[2], pu3=pk2[3];
            float2 p0=h2f(pu0.x),p1=h2f(pu0.y),p2=h2f(pu1.x),p3=h2f(pu1.y);
            float2 p4=h2f(pu2.x),p5=h2f(pu2.y),p6=h2f(pu3.x),p7=h2f(pu3.y);
#pragma unroll
            for (int r=0;r<BB;r++){
                const float4* q4 = (const float4*)(qh_s + r*E_ + h*HD_);
                float4 q0=q4[0],q1=q4[1],q2=q4[2],q3=q4[3];
                float d =
                  q0.x*p0.x+q0.y*p0.y+q0.z*p1.x+q0.w*p1.y
                + q1.x*p2.x+q1.y*p2.y+q1.z*p3.x+q1.w*p3.y
                + q2.x*p4.x+q2.y*p4.y+q2.z*p5.x+q2.w*p5.y
                + q3.x*p6.x+q3.y*p6.y+q3.z*p7.x+q3.w*p7.y;
                float se = __half2float(SE_s[(r*H_+h)*V_ + myidx[r]]);
                a_s[(r*H_+h)*T_ + t] = __float2half(fmaf(d, 0.25f, se));
            }
        }
    }
    __syncthreads();

    {   // swap tables to Ev/Pv + warp-per-row softmax (disjoint smem regions)
        const uint4* s4 = (const uint4*)g_Ev; uint4* d4 = (uint4*)Ek_s;
        for (int i = tid; i < (V_*EP)/8; i += 256) d4[i] = s4[i];
        const uint4* s5 = (const uint4*)g_Pv; uint4* d5 = (uint4*)Pk_s;
        for (int i = tid; i < (T_*EP)/8; i += 256) d5[i] = s5[i];

        int wid = tid>>5, lane = tid&31;
        int r = wid;
#pragma unroll
        for (int h=0;h<H_;h++){
            __half* row = a_s + (r*H_+h)*T_;
            float v[8]; float m = -1e30f;
#pragma unroll
            for (int j=0;j<8;j++){ v[j]=__half2float(row[lane+32*j]); m = fmaxf(m, v[j]); }
#pragma unroll
            for (int o=16;o;o>>=1) m = fmaxf(m, __shfl_xor_sync(0xffffffffu, m, o));
            float ssum = 0.f;
#pragma unroll
            for (int j=0;j<8;j++){ v[j]=__expf(v[j]-m); ssum += v[j]; }
#pragma unroll
            for (int o=16;o;o>>=1) ssum += __shfl_xor_sync(0xffffffffu, ssum, o);
            float inv = 1.f/ssum;
#pragma unroll
            for (int j=0;j<8;j++) row[lane+32*j] = __float2half(v[j]*inv);
        }
    }
    __syncthreads();

    if (tid < BB*24) {                      // ctx: thread = (row, 4-wide col group)
        int r = tid/24, g = tid%24;
        int h = g>>2, col = g*4;
        const __half* arow = a_s + (r*H_+h)*T_;
        const unsigned short* irow = idx_s + r*T_;
        float ax=0.f, ay=0.f, az=0.f, aw=0.f;
#pragma unroll 4
        for (int t2=0;t2<T_;t2++){
            float av = __half2float(arow[t2]);
            int   ix = irow[t2];
            uint2 eu = *(const uint2*)(Ek_s + ix*EP + col);   // holds Ev now
            uint2 pu = *(const uint2*)(Pk_s + t2*EP + col);   // holds Pv now
            float2 e0=h2f(eu.x), e1=h2f(eu.y), p0=h2f(pu.x), p1=h2f(pu.y);
            ax += av*(e0.x+p0.x); ay += av*(e0.y+p0.y);
            az += av*(e1.x+p1.x); aw += av*(e1.y+p1.y);
        }
        *(float4*)(g_ctx + (b0+r)*E_ + col) = make_float4(ax,ay,az,aw);
    }
}

// ==================== K3: fused GRU + memory gate + LN + head ====================
__constant__ signed char c_tmap[8][2] = {  // balanced warp->tile map (k-iters <= 384)
    {0,-1},{1,-1},{2,-1},{3,-1},{4,9},{5,10},{6,8},{7,11}
};

__global__ __launch_bounds__(256) void k3_gru(
    const int* __restrict__ cidx, const float* __restrict__ hidden,
    const float* __restrict__ memory, const float* __restrict__ mwb,
    const float* __restrict__ pgb,
    float* __restrict__ out_logits, float* __restrict__ out_hidden,
    float* __restrict__ out_memory)
{
    extern __shared__ float sm[];
    float* XsT   = sm;                  // 288*36 = 10368 (k-major, 36-row pad)
    float* Os    = sm + 10368;          // 384*33 = 12672 -> 23040
    float* mu_s  = sm + 23040;          // 32
    float* rs_s  = sm + 23072;          // 32
    int*   cidx_s= (int*)(sm + 23104);  // 32 -> 23136 floats

    const int tid = threadIdx.x;
    const int b0  = blockIdx.x * RB;
    const int wid = tid>>5, lane = tid&31;

    if (tid < RB) cidx_s[tid] = cidx[b0+tid];
    for (int i = tid; i < RB*E_; i += 256){
        int r = i/E_, c = i%E_;
        XsT[c*36 + r]        = g_ctx[(b0+r)*E_ + c];
        XsT[(E_+c)*36 + r]   = memory[(b0+r)*E_ + c];
        XsT[(2*E_+c)*36 + r] = hidden[(b0+r)*E_ + c];
    }
    __syncthreads();

    // stage-1 fused GEMM with packed f32x2 FMA:
    // Os[o][r] = sum_k X[r][k]*Wbig[k][o] + Gbig[cidx[r]][o]
#pragma unroll
    for (int ti = 0; ti < 2; ti++){
        int tile = c_tmap[wid][ti];
        if (tile < 0) continue;
        int o  = tile*32 + lane;
        int k0 = (tile >= 9) ? 192 : 0;
        int k1 = (tile < 6)  ? 288 : ((tile < 9) ? 192 : 288);
        unsigned long long acc2[16];
#pragma unroll
        for (int j=0;j<16;j++) acc2[j]=0ull;
#pragma unroll 4
        for (int k=k0;k<k1;k++){
            float wv = g_Wbig[k*GO + o];
            unsigned long long wv2;
            asm("mov.b64 %0, {%1, %1};" : "=l"(wv2) : "f"(wv));
            const ulonglong2* xr = (const ulonglong2*)(XsT + k*36);
#pragma unroll
            for (int j=0;j<8;j++){
                ulonglong2 x = xr[j];           // 4 floats = 2 packed f32x2
                FMA2(acc2[2*j],   x.x, wv2);
                FMA2(acc2[2*j+1], x.y, wv2);
            }
        }
        const float* gb = g_Gbig;               // unpack + bias + store
#pragma unroll
        for (int j=0;j<16;j++){
            float lo, hi;
            asm("mov.b64 {%0, %1}, %2;" : "=f"(lo), "=f"(hi) : "l"(acc2[j]));
            int r0 = 2*j, r1 = 2*j+1;
            Os[o*33 + r0] = lo + gb[cidx_s[r0]*GO + o];
            Os[o*33 + r1] = hi + gb[cidx_s[r1]*GO + o];
        }
    }
    __syncthreads();

    // GRU elementwise -> new_hidden; stash nh^T in XsT[0:96)
    for (int i = tid; i < RB*E_; i += 256){
        int r = i/E_, e = i%E_;
        float orv = Os[e*33+r];
        float ozv = Os[(E_+e)*33+r];
        float oin = Os[(2*E_+e)*33+r];
        float ohn = Os[(3*E_+e)*33+r];
        float rr = 1.f/(1.f+__expf(-orv));
        float zz = 1.f/(1.f+__expf(-ozv));
        float nn = tanhf(oin + rr*ohn);
        float hp = XsT[(2*E_+e)*36 + r];
        float nh = (1.f-zz)*nn + zz*hp;
        XsT[e*36 + r] = nh;
        out_hidden[(b0+r)*E_ + e] = nh;
    }
    __syncthreads();

    // per-row mean / rstd (8 threads per row)
    {
        int r = tid>>3, l8 = tid&7;
        float s=0.f, sq=0.f;
        for (int e=l8; e<E_; e+=8){ float v = XsT[e*36+r]; s += v; sq += v*v; }
#pragma unroll
        for (int o=4;o;o>>=1){
            s  += __shfl_xor_sync(0xffffffffu, s,  o);
            sq += __shfl_xor_sync(0xffffffffu, sq, o);
        }
        if (l8==0){
            float mu = s*(1.f/E_);
            float var = sq*(1.f/E_) - mu*mu;
            mu_s[r] = mu;
            rs_s[r] = rsqrtf(var + 1e-5f);
        }
    }
    __syncthreads();

    // stage-2 GEMM (packed f32x2): Os[o][r] = sum_e nh[r][e]*W2[e][o]
    for (int tile = wid; tile < 7; tile += 8){
        int o = tile*32 + lane;
        unsigned long long acc2[16];
#pragma unroll
        for (int j=0;j<16;j++) acc2[j]=0ull;
#pragma unroll 4
        for (int k=0;k<E_;k++){
            float wv = g_W2[k*S2O + o];
            unsigned long long wv2;
            asm("mov.b64 %0, {%1, %1};" : "=l"(wv2) : "f"(wv));
            const ulonglong2* xr = (const ulonglong2*)(XsT + k*36);
#pragma unroll
            for (int j=0;j<8;j++){
                ulonglong2 x = xr[j];
                FMA2(acc2[2*j],   x.x, wv2);
                FMA2(acc2[2*j+1], x.y, wv2);
            }
        }
#pragma unroll
        for (int j=0;j<16;j++){
            float lo, hi;
            asm("mov.b64 {%0, %1}, %2;" : "=f"(lo), "=f"(hi) : "l"(acc2[j]));
            Os[o*33 + 2*j]   = lo;
            Os[o*33 + 2*j+1] = hi;
        }
    }
    __syncthreads();

    // epilogue: memory gate
    float pgb0 = pgb[0];
    for (int i = tid; i < RB*E_; i += 256){
        int r = i/E_, e = i%E_;
        float p    = 1.f/(1.f+__expf(-(Os[96*33+r] + pgb0)));
        float cand = tanhf(Os[e*33+r] + mwb[e]);
        float mem  = XsT[(E_+e)*36 + r];
        out_memory[(b0+r)*E_ + e] = (1.f-p)*mem + p*cand;
    }
    // epilogue: logits via folded LN+head
    for (int i = tid; i < RB*V_; i += 256){
        int r = i/V_, v = i%V_;
        float y = Os[(97+v)*33 + r];
        out_logits[(b0+r)*V_ + v] = rs_s[r]*(y - mu_s[r]*g_hg[v]) + g_hc1[v];
    }
}

// ================================== launch ==================================
extern "C" void kernel_launch(void* const* d_in, const int* in_sizes, int n_in,
                              void* d_out, int out_size)
{
    const int*   cidx = (const int*)  d_in[0];
    const int*   hist = (const int*)  d_in[1];
    const float* hid  = (const float*)d_in[2];
    const float* mem  = (const float*)d_in[3];
    const float* tok  = (const float*)d_in[4];
    const float* pos  = (const float*)d_in[5];
    const float* ipw  = (const float*)d_in[6];
    const float* ipb  = (const float*)d_in[7];
    const float* opw  = (const float*)d_in[8];
    const float* opb  = (const float*)d_in[9];
    const float* gih  = (const float*)d_in[10];
    const float* ghh  = (const float*)d_in[11];
    const float* gbih = (const float*)d_in[12];
    const float* gbhh = (const float*)d_in[13];
    const float* pgw  = (const float*)d_in[14];
    const float* pgb  = (const float*)d_in[15];
    const float* mww  = (const float*)d_in[16];
    const float* mwb  = (const float*)d_in[17];
    const float* lng  = (const float*)d_in[18];
    const float* lnb  = (const float*)d_in[19];
    const float* hdw  = (const float*)d_in[20];
    const float* hdb  = (const float*)d_in[21];

    float* out         = (float*)d_out;
    float* out_logits  = out;
    float* out_hidden  = out + (size_t)B_*V_;
    float* out_memory  = out + (size_t)B_*V_ + (size_t)B_*E_;

    cudaFuncSetAttribute(k2_attn, cudaFuncAttributeMaxDynamicSharedMemorySize,
                         K2_SMEM_BYTES);
    cudaFuncSetAttribute(k3_gru,  cudaFuncAttributeMaxDynamicSharedMemorySize,
                         K3_SMEM_FLOATS*4);

    const int k1_total = 3*V_*E_ + 2*T_*E_ + E_ + V_*GO + 288*GO + E_*S2O + 2*V_;
    k1_precompute<<<(k1_total+255)/256, 256>>>(tok,pos,ipw,ipb,opw,opb,
                                               gih,ghh,gbih,gbhh,pgw,mww,
                                               lng,lnb,hdw,hdb);
    k2_attn<<<B_/BB, 256, K2_SMEM_BYTES>>>(hist);
    k3_gru <<<B_/RB, 256, K3_SMEM_FLOATS*4>>>(cidx, hid, mem, mwb, pgb,
                                              out_logits, out_hidden, out_memory);
}

// round 9
// speedup vs baseline: 1.7061x; 1.0825x over previous
#include <cuda_runtime.h>
#include <cuda_fp16.h>
#include <cuda_bf16.h>
#include <math.h>

#define B_  4096
#define T_  256
#define E_  96
#define H_  6
#define HD_ 16
#define V_  98
#define EP  100     // padded row stride (halves) for Ek/Ev/Pk/Pv tables
#define GO  384     // stage-1 fused outputs: [r|z (192) | i_n (96) | h_n (96)]
#define S2O 224     // stage-2 padded outputs: [cand(96) | p(1) | head(98) | pad]
#define BB  8       // batch rows per block in K2
#define RB  32      // batch rows per block in K3

#define K2_SMEM_BYTES 111952
#define K3_SMEM_FLOATS 23136

// -------- persistent scratch (__device__ globals; no allocation allowed) --------
__device__ float g_Eq[V_*E_];
__device__ __align__(16) __half g_Ek[V_*EP];
__device__ __align__(16) __half g_Ev[V_*EP];
__device__ __align__(16) __half g_Pk[T_*EP];
__device__ __align__(16) __half g_Pv[T_*EP];
__device__ float g_pq[E_];
__device__ float g_Gbig[V_*GO];     // per-vocab token contribution + all bias constants
__device__ float g_Wbig[288*GO];    // fused GRU weights; input X = [ctx_raw|memory|hidden]
__device__ float g_W2[E_*S2O];      // fused stage-2 weights [mw^T | pg | (ln_g*head)^T | pad]
__device__ float g_hg[V_];          // sum_e ln_g[e]*head_w[v][e]
__device__ float g_hc1[V_];         // sum_e ln_b[e]*head_w[v][e] + head_b[v]
__device__ float g_ctx[B_*E_];      // raw (pre-out_proj) attention context

__device__ __forceinline__ float dot4(float4 a, float4 b, float s){
    s = fmaf(a.x, b.x, s); s = fmaf(a.y, b.y, s);
    s = fmaf(a.z, b.z, s); s = fmaf(a.w, b.w, s);
    return s;
}
__device__ __forceinline__ float2 h2f(unsigned int u){
    return __half22float2(*reinterpret_cast<const __half2*>(&u));
}
// packed fp32x2 FMA (Blackwell): d = a*b + d, bit-exact IEEE fp32 per lane half
#define FMA2(d,a,b) asm("fma.rn.f32x2 %0, %1, %2, %0;" : "+l"(d) : "l"(a), "l"(b))

// cooperative 96-dot: 8 lanes, each reads 3 contiguous float4 of each row
// (nL ~4 lines/warp-load instead of ~32), butterfly-reduce within the 8-group.
__device__ __forceinline__ float gdot96(const float* a, const float* b,
                                        int l, unsigned gmask){
    const float4* a4 = (const float4*)a;
    const float4* b4 = (const float4*)b;
    float s = dot4(a4[l],    b4[l],    0.f);
    s       = dot4(a4[l+8],  b4[l+8],  s);
    s       = dot4(a4[l+16], b4[l+16], s);
    s += __shfl_xor_sync(gmask, s, 4);
    s += __shfl_xor_sync(gmask, s, 2);
    s += __shfl_xor_sync(gmask, s, 1);
    return s;
}

// ================= K1a: precompute, dot jobs (8 lanes / output) =================
#define N_EQ   (V_*E_)      // 28224
#define N_EK   (V_*E_)
#define N_EV   (V_*E_)
#define N_PK   (T_*E_)      // 24576
#define N_PV   (T_*E_)
#define N_PQ   (E_)
#define N_GB   (V_*288)     // 28224
#define N_WA   (E_*288)     // 27648
#define N_HG   (V_)
#define N_HC   (V_)
#define K1A_GROUPS (N_EQ+N_EK+N_EV+N_PK+N_PV+N_PQ+N_GB+N_WA+N_HG+N_HC) // 189988

__global__ void k1a_dots(
    const float* __restrict__ tok,  const float* __restrict__ pos,
    const float* __restrict__ ipw,  const float* __restrict__ ipb,
    const float* __restrict__ opw,  const float* __restrict__ opb,
    const float* __restrict__ gih,  const float* __restrict__ gbih,
    const float* __restrict__ gbhh, const float* __restrict__ lng,
    const float* __restrict__ lnb,  const float* __restrict__ headw,
    const float* __restrict__ headb)
{
    int g = (blockIdx.x*blockDim.x + threadIdx.x) >> 3;
    if (g >= K1A_GROUPS) return;
    const int l = threadIdx.x & 7;
    const unsigned gmask = 0xFFu << (threadIdx.x & 24);

    if (g < N_EQ){                                  // Eq = tok @ Wq^T (fp32)
        int v=g/E_, e=g%E_;
        float s = gdot96(tok+v*E_, ipw+e*E_, l, gmask);
        if (!l) g_Eq[v*E_+e] = s;
        return;
    }
    g -= N_EQ;
    if (g < N_EK){                                  // Ek (fp16)
        int v=g/E_, e=g%E_;
        float s = gdot96(tok+v*E_, ipw+(E_+e)*E_, l, gmask);
        if (!l) g_Ek[v*EP+e] = __float2half(s);
        return;
    }
    g -= N_EK;
    if (g < N_EV){                                  // Ev (fp16)
        int v=g/E_, e=g%E_;
        float s = gdot96(tok+v*E_, ipw+(2*E_+e)*E_, l, gmask);
        if (!l) g_Ev[v*EP+e] = __float2half(s);
        return;
    }
    g -= N_EV;
    if (g < N_PK){                                  // Pk = pos@Wk^T + bk (fp16)
        int t=g/E_, e=g%E_;
        float s = gdot96(pos+t*E_, ipw+(E_+e)*E_, l, gmask);
        if (!l) g_Pk[t*EP+e] = __float2half(s + ipb[E_+e]);
        return;
    }
    g -= N_PK;
    if (g < N_PV){                                  // Pv (fp16)
        int t=g/E_, e=g%E_;
        float s = gdot96(pos+t*E_, ipw+(2*E_+e)*E_, l, gmask);
        if (!l) g_Pv[t*EP+e] = __float2half(s + ipb[2*E_+e]);
        return;
    }
    g -= N_PV;
    if (g < N_PQ){                                  // pq
        int e=g;
        float s = gdot96(pos+(T_-1)*E_, ipw+e*E_, l, gmask);
        if (!l) g_pq[e] = s + ipb[e];
        return;
    }
    g -= N_PQ;
    if (g < N_GB){                                  // Gbig o<288 (dual 96-dot)
        int v=g/288, o=g%288;
        float s = gdot96(tok+v*E_, gih+o*288, l, gmask)
                + gdot96(opb,      gih+o*288+E_, l, gmask);
        if (!l){
            s += gbih[o];
            if (o < 192) s += gbhh[o];
            g_Gbig[v*GO+o] = s;
        }
        return;
    }
    g -= N_GB;
    if (g < N_WA){                                  // Wbig k<96, o<288 (opw-col dot)
        int k=g/288, o=g%288;
        const float* gr = gih + o*288 + E_;
        float s = 0.f;
#pragma unroll
        for (int st=0; st<12; st++){
            int j = l + 8*st;
            s = fmaf(gr[j], opw[j*E_+k], s);
        }
        s += __shfl_xor_sync(gmask, s, 4);
        s += __shfl_xor_sync(gmask, s, 2);
        s += __shfl_xor_sync(gmask, s, 1);
        if (!l) g_Wbig[k*GO+o] = s;
        return;
    }
    g -= N_WA;
    if (g < N_HG){                                  // hg
        float s = gdot96(lng, headw+g*E_, l, gmask);
        if (!l) g_hg[g] = s;
        return;
    }
    g -= N_HG;
    {                                               // hc1
        float s = gdot96(lnb, headw+g*E_, l, gmask);
        if (!l) g_hc1[g] = s + headb[g];
    }
}

// ================= K1b: precompute, copies / zeros (1 thread / elem) =============
#define K1B_TOTAL (V_*E_ + E_*E_ + 192*GO + E_*S2O)   // 9408+9216+73728+21504 = 113856

__global__ void k1b_copies(
    const float* __restrict__ gih,  const float* __restrict__ ghh,
    const float* __restrict__ gbhh, const float* __restrict__ pgw,
    const float* __restrict__ mww,  const float* __restrict__ lng,
    const float* __restrict__ headw)
{
    int i = blockIdx.x*blockDim.x + threadIdx.x;
    if (i < V_*E_){                                 // Gbig o>=288: h_n bias
        int v=i/E_, n=i%E_;
        g_Gbig[v*GO + 288 + n] = gbhh[192+n];
        return;
    }
    i -= V_*E_;
    if (i < E_*E_){                                 // Wbig k<96, o>=288: zero
        int k=i/E_, o=288 + i%E_;
        g_Wbig[k*GO+o] = 0.f;
        return;
    }
    i -= E_*E_;
    if (i < 192*GO){                                // Wbig k in [96,288)
        int k = 96 + i/GO, o = i%GO;
        float s = 0.f;
        if (k < 192){
            int m = k - 96;
            if (o < 288) s = gih[o*288 + 2*E_ + m];
        } else {
            int hh = k - 192;
            if (o < 192)       s = ghh[o*E_+hh];
            else if (o >= 288) s = ghh[(192+(o-288))*E_+hh];
        }
        g_Wbig[k*GO+o] = s;
        return;
    }
    i -= 192*GO;
    if (i < E_*S2O){                                // W2
        int e=i/S2O, o=i%S2O; float s=0.f;
        if (o < 96)       s = mww[o*E_+e];
        else if (o == 96) s = pgw[e];
        else if (o < 195) s = headw[(o-97)*E_+e]*lng[e];
        g_W2[e*S2O+o] = s;
    }
}

// ================================ K2: attention ================================
// smem: Ek 19600 | Pk 51200 | qh 3072 | a 24576 | idx 4096 | SE 9408+pad = 111952 B
// launch_bounds(256,2) guarantees regs<=128 -> 2 CTAs/SM for the fp16 layout.
__global__ __launch_bounds__(256, 2) void k2_attn(const int* __restrict__ hist)
{
    extern __shared__ char smc[];
    __half* Ek_s = (__half*)smc;                            // 9800 halves
    __half* Pk_s = (__half*)(smc + 19600);                  // 25600 halves
    float*  qh_s = (float*)(smc + 70800);                   // 768 floats
    __half* a_s  = (__half*)(smc + 73872);                  // 12288 halves
    unsigned short* idx_s = (unsigned short*)(smc + 98448); // 2048 u16
    __half* SE_s = (__half*)(smc + 102544);                 // 48*98 = 4704 halves

    const int tid = threadIdx.x;
    const int b0  = blockIdx.x * BB;

    for (int i = tid; i < BB*T_; i += 256)
        idx_s[i] = (unsigned short)hist[(b0 + (i>>8))*T_ + (i&255)];
    {   // stage Ek, Pk (fp16, uint4 = 8 halves)
        const uint4* s4 = (const uint4*)g_Ek; uint4* d4 = (uint4*)Ek_s;
        for (int i = tid; i < (V_*EP)/8; i += 256) d4[i] = s4[i];
        const uint4* s5 = (const uint4*)g_Pk; uint4* d5 = (uint4*)Pk_s;
        for (int i = tid; i < (T_*EP)/8; i += 256) d5[i] = s5[i];
    }
    __syncthreads();

    for (int i = tid; i < BB*E_; i += 256) {            // qh = Eq[last] + pq (fp32)
        int r = i / E_, e = i % E_;
        int li = idx_s[r*T_ + (T_-1)];
        qh_s[i] = g_Eq[li*E_+e] + g_pq[e];
    }
    __syncthreads();

    // SE phase: SE[r,h,v] = 0.25 * q[r,h] · Ek[v]
    for (int i = tid; i < H_*V_; i += 256){
        int h = i / V_, v = i % V_;
        const uint2* e2 = (const uint2*)(Ek_s + v*EP + h*HD_);
        uint2 u0=e2[0],u1=e2[1],u2=e2[2],u3=e2[3];
        float2 e0=h2f(u0.x),e1=h2f(u0.y),e2f_=h2f(u1.x),e3=h2f(u1.y);
        float2 e4=h2f(u2.x),e5=h2f(u2.y),e6=h2f(u3.x),e7=h2f(u3.y);
#pragma unroll
        for (int r=0;r<BB;r++){
            const float4* q4 = (const float4*)(qh_s + r*E_ + h*HD_);
            float4 q0=q4[0],q1=q4[1],q2=q4[2],q3=q4[3];
            float s =
              q0.x*e0.x+q0.y*e0.y+q0.z*e1.x+q0.w*e1.y
            + q1.x*e2f_.x+q1.y*e2f_.y+q1.z*e3.x+q1.w*e3.y
            + q2.x*e4.x+q2.y*e4.y+q2.z*e5.x+q2.w*e5.y
            + q3.x*e6.x+q3.y*e6.y+q3.z*e7.x+q3.w*e7.y;
            SE_s[(r*H_+h)*V_ + v] = __float2half(s * 0.25f);
        }
    }
    __syncthreads();

    {   // score phase: thread t owns position t; score = SE[r,h,idx] + 0.25*q·Pk[t]
        const int t = tid;
        int myidx[BB];
#pragma unroll
        for (int r=0;r<BB;r++) myidx[r] = idx_s[r*T_+t];
#pragma unroll
        for (int h=0;h<H_;h++){
            const uint2* pk2 = (const uint2*)(Pk_s + t*EP + h*HD_);
            uint2 pu0=pk2[0], pu1=pk2[1], pu2=pk2[2], pu3=pk2[3];
            float2 p0=h2f(pu0.x),p1=h2f(pu0.y),p2=h2f(pu1.x),p3=h2f(pu1.y);
            float2 p4=h2f(pu2.x),p5=h2f(pu2.y),p6=h2f(pu3.x),p7=h2f(pu3.y);
#pragma unroll
            for (int r=0;r<BB;r++){
                const float4* q4 = (const float4*)(qh_s + r*E_ + h*HD_);
                float4 q0=q4[0],q1=q4[1],q2=q4[2],q3=q4[3];
                float d =
                  q0.x*p0.x+q0.y*p0.y+q0.z*p1.x+q0.w*p1.y
                + q1.x*p2.x+q1.y*p2.y+q1.z*p3.x+q1.w*p3.y
                + q2.x*p4.x+q2.y*p4.y+q2.z*p5.x+q2.w*p5.y
                + q3.x*p6.x+q3.y*p6.y+q3.z*p7.x+q3.w*p7.y;
                float se = __half2float(SE_s[(r*H_+h)*V_ + myidx[r]]);
                a_s[(r*H_+h)*T_ + t] = __float2half(fmaf(d, 0.25f, se));
            }
        }
    }
    __syncthreads();

    {   // swap tables to Ev/Pv + warp-per-row softmax (disjoint smem regions)
        const uint4* s4 = (const uint4*)g_Ev; uint4* d4 = (uint4*)Ek_s;
        for (int i = tid; i < (V_*EP)/8; i += 256) d4[i] = s4[i];
        const uint4* s5 = (const uint4*)g_Pv; uint4* d5 = (uint4*)Pk_s;
        for (int i = tid; i < (T_*EP)/8; i += 256) d5[i] = s5[i];

        int wid = tid>>5, lane = tid&31;
        int r = wid;
#pragma unroll
        for (int h=0;h<H_;h++){
            __half* row = a_s + (r*H_+h)*T_;
            float v[8]; float m = -1e30f;
#pragma unroll
            for (int j=0;j<8;j++){ v[j]=__half2float(row[lane+32*j]); m = fmaxf(m, v[j]); }
#pragma unroll
            for (int o=16;o;o>>=1) m = fmaxf(m, __shfl_xor_sync(0xffffffffu, m, o));
            float ssum = 0.f;
#pragma unroll
            for (int j=0;j<8;j++){ v[j]=__expf(v[j]-m); ssum += v[j]; }
#pragma unroll
            for (int o=16;o;o>>=1) ssum += __shfl_xor_sync(0xffffffffu, ssum, o);
            float inv = 1.f/ssum;
#pragma unroll
            for (int j=0;j<8;j++) row[lane+32*j] = __float2half(v[j]*inv);
        }
    }
    __syncthreads();

    if (tid < BB*24) {                      // ctx: thread = (row, 4-wide col group)
        int r = tid/24, g = tid%24;
        int h = g>>2, col = g*4;
        const __half* arow = a_s + (r*H_+h)*T_;
        const unsigned short* irow = idx_s + r*T_;
        float ax=0.f, ay=0.f, az=0.f, aw=0.f;
#pragma unroll 4
        for (int t2=0;t2<T_;t2++){
            float av = __half2float(arow[t2]);
            int   ix = irow[t2];
            uint2 eu = *(const uint2*)(Ek_s + ix*EP + col);   // holds Ev now
            uint2 pu = *(const uint2*)(Pk_s + t2*EP + col);   // holds Pv now
            float2 e0=h2f(eu.x), e1=h2f(eu.y), p0=h2f(pu.x), p1=h2f(pu.y);
            ax += av*(e0.x+p0.x); ay += av*(e0.y+p0.y);
            az += av*(e1.x+p1.x); aw += av*(e1.y+p1.y);
        }
        *(float4*)(g_ctx + (b0+r)*E_ + col) = make_float4(ax,ay,az,aw);
    }
}

// ==================== K3: fused GRU + memory gate + LN + head ====================
__constant__ signed char c_tmap[8][2] = {  // balanced warp->tile map (k-iters <= 384)
    {0,-1},{1,-1},{2,-1},{3,-1},{4,9},{5,10},{6,8},{7,11}
};

__global__ __launch_bounds__(256) void k3_gru(
    const int* __restrict__ cidx, const float* __restrict__ hidden,
    const float* __restrict__ memory, const float* __restrict__ mwb,
    const float* __restrict__ pgb,
    float* __restrict__ out_logits, float* __restrict__ out_hidden,
    float* __restrict__ out_memory)
{
    extern __shared__ float sm[];
    float* XsT   = sm;                  // 288*36 = 10368 (k-major, 36-row pad)
    float* Os    = sm + 10368;          // 384*33 = 12672 -> 23040
    float* mu_s  = sm + 23040;          // 32
    float* rs_s  = sm + 23072;          // 32
    int*   cidx_s= (int*)(sm + 23104);  // 32 -> 23136 floats

    const int tid = threadIdx.x;
    const int b0  = blockIdx.x * RB;
    const int wid = tid>>5, lane = tid&31;

    if (tid < RB) cidx_s[tid] = cidx[b0+tid];
    for (int i = tid; i < RB*E_; i += 256){
        int r = i/E_, c = i%E_;
        XsT[c*36 + r]        = g_ctx[(b0+r)*E_ + c];
        XsT[(E_+c)*36 + r]   = memory[(b0+r)*E_ + c];
        XsT[(2*E_+c)*36 + r] = hidden[(b0+r)*E_ + c];
    }
    __syncthreads();

    // stage-1 fused GEMM with packed f32x2 FMA; unroll 8 keeps 8 Wbig LDGs in
    // flight against ~250-cyc L2 latency.
#pragma unroll
    for (int ti = 0; ti < 2; ti++){
        int tile = c_tmap[wid][ti];
        if (tile < 0) continue;
        int o  = tile*32 + lane;
        int k0 = (tile >= 9) ? 192 : 0;
        int k1 = (tile < 6)  ? 288 : ((tile < 9) ? 192 : 288);
        unsigned long long acc2[16];
#pragma unroll
        for (int j=0;j<16;j++) acc2[j]=0ull;
#pragma unroll 8
        for (int k=k0;k<k1;k++){
            float wv = g_Wbig[k*GO + o];
            unsigned long long wv2;
            asm("mov.b64 %0, {%1, %1};" : "=l"(wv2) : "f"(wv));
            const ulonglong2* xr = (const ulonglong2*)(XsT + k*36);
#pragma unroll
            for (int j=0;j<8;j++){
                ulonglong2 x = xr[j];           // 4 floats = 2 packed f32x2
                FMA2(acc2[2*j],   x.x, wv2);
                FMA2(acc2[2*j+1], x.y, wv2);
            }
        }
        const float* gb = g_Gbig;               // unpack + bias + store
#pragma unroll
        for (int j=0;j<16;j++){
            float lo, hi;
            asm("mov.b64 {%0, %1}, %2;" : "=f"(lo), "=f"(hi) : "l"(acc2[j]));
            int r0 = 2*j, r1 = 2*j+1;
            Os[o*33 + r0] = lo + gb[cidx_s[r0]*GO + o];
            Os[o*33 + r1] = hi + gb[cidx_s[r1]*GO + o];
        }
    }
    __syncthreads();

    // GRU elementwise -> new_hidden; stash nh^T in XsT[0:96)
    for (int i = tid; i < RB*E_; i += 256){
        int r = i/E_, e = i%E_;
        float orv = Os[e*33+r];
        float ozv = Os[(E_+e)*33+r];
        float oin = Os[(2*E_+e)*33+r];
        float ohn = Os[(3*E_+e)*33+r];
        float rr = 1.f/(1.f+__expf(-orv));
        float zz = 1.f/(1.f+__expf(-ozv));
        float nn = tanhf(oin + rr*ohn);
        float hp = XsT[(2*E_+e)*36 + r];
        float nh = (1.f-zz)*nn + zz*hp;
        XsT[e*36 + r] = nh;
        out_hidden[(b0+r)*E_ + e] = nh;
    }
    __syncthreads();

    // per-row mean / rstd (8 threads per row)
    {
        int r = tid>>3, l8 = tid&7;
        float s=0.f, sq=0.f;
        for (int e=l8; e<E_; e+=8){ float v = XsT[e*36+r]; s += v; sq += v*v; }
#pragma unroll
        for (int o=4;o;o>>=1){
            s  += __shfl_xor_sync(0xffffffffu, s,  o);
            sq += __shfl_xor_sync(0xffffffffu, sq, o);
        }
        if (l8==0){
            float mu = s*(1.f/E_);
            float var = sq*(1.f/E_) - mu*mu;
            mu_s[r] = mu;
            rs_s[r] = rsqrtf(var + 1e-5f);
        }
    }
    __syncthreads();

    // stage-2 GEMM (packed f32x2): Os[o][r] = sum_e nh[r][e]*W2[e][o]
    for (int tile = wid; tile < 7; tile += 8){
        int o = tile*32 + lane;
        unsigned long long acc2[16];
#pragma unroll
        for (int j=0;j<16;j++) acc2[j]=0ull;
#pragma unroll 8
        for (int k=0;k<E_;k++){
            float wv = g_W2[k*S2O + o];
            unsigned long long wv2;
            asm("mov.b64 %0, {%1, %1};" : "=l"(wv2) : "f"(wv));
            const ulonglong2* xr = (const ulonglong2*)(XsT + k*36);
#pragma unroll
            for (int j=0;j<8;j++){
                ulonglong2 x = xr[j];
                FMA2(acc2[2*j],   x.x, wv2);
                FMA2(acc2[2*j+1], x.y, wv2);
            }
        }
#pragma unroll
        for (int j=0;j<16;j++){
            float lo, hi;
            asm("mov.b64 {%0, %1}, %2;" : "=f"(lo), "=f"(hi) : "l"(acc2[j]));
            Os[o*33 + 2*j]   = lo;
            Os[o*33 + 2*j+1] = hi;
        }
    }
    __syncthreads();

    // epilogue: memory gate
    float pgb0 = pgb[0];
    for (int i = tid; i < RB*E_; i += 256){
        int r = i/E_, e = i%E_;
        float p    = 1.f/(1.f+__expf(-(Os[96*33+r] + pgb0)));
        float cand = tanhf(Os[e*33+r] + mwb[e]);
        float mem  = XsT[(E_+e)*36 + r];
        out_memory[(b0+r)*E_ + e] = (1.f-p)*mem + p*cand;
    }
    // epilogue: logits via folded LN+head
    for (int i = tid; i < RB*V_; i += 256){
        int r = i/V_, v = i%V_;
        float y = Os[(97+v)*33 + r];
        out_logits[(b0+r)*V_ + v] = rs_s[r]*(y - mu_s[r]*g_hg[v]) + g_hc1[v];
    }
}

// ================================== launch ==================================
extern "C" void kernel_launch(void* const* d_in, const int* in_sizes, int n_in,
                              void* d_out, int out_size)
{
    const int*   cidx = (const int*)  d_in[0];
    const int*   hist = (const int*)  d_in[1];
    const float* hid  = (const float*)d_in[2];
    const float* mem  = (const float*)d_in[3];
    const float* tok  = (const float*)d_in[4];
    const float* pos  = (const float*)d_in[5];
    const float* ipw  = (const float*)d_in[6];
    const float* ipb  = (const float*)d_in[7];
    const float* opw  = (const float*)d_in[8];
    const float* opb  = (const float*)d_in[9];
    const float* gih  = (const float*)d_in[10];
    const float* ghh  = (const float*)d_in[11];
    const float* gbih = (const float*)d_in[12];
    const float* gbhh = (const float*)d_in[13];
    const float* pgw  = (const float*)d_in[14];
    const float* pgb  = (const float*)d_in[15];
    const float* mww  = (const float*)d_in[16];
    const float* mwb  = (const float*)d_in[17];
    const float* lng  = (const float*)d_in[18];
    const float* lnb  = (const float*)d_in[19];
    const float* hdw  = (const float*)d_in[20];
    const float* hdb  = (const float*)d_in[21];

    float* out         = (float*)d_out;
    float* out_logits  = out;
    float* out_hidden  = out + (size_t)B_*V_;
    float* out_memory  = out + (size_t)B_*V_ + (size_t)B_*E_;

    cudaFuncSetAttribute(k2_attn, cudaFuncAttributeMaxDynamicSharedMemorySize,
                         K2_SMEM_BYTES);
    cudaFuncSetAttribute(k3_gru,  cudaFuncAttributeMaxDynamicSharedMemorySize,
                         K3_SMEM_FLOATS*4);

    const int k1a_blocks = (K1A_GROUPS*8 + 255) / 256;   // 5938
    const int k1b_blocks = (K1B_TOTAL   + 255) / 256;    // 445
    k1a_dots<<<k1a_blocks, 256>>>(tok,pos,ipw,ipb,opw,opb,
                                  gih,gbih,gbhh,lng,lnb,hdw,hdb);
    k1b_copies<<<k1b_blocks, 256>>>(gih,ghh,gbhh,pgw,mww,lng,hdw);
    k2_attn<<<B_/BB, 256, K2_SMEM_BYTES>>>(hist);
    k3_gru <<<B_/RB, 256, K3_SMEM_FLOATS*4>>>(cidx, hid, mem, mwb, pgb,
                                              out_logits, out_hidden, out_memory);
}

// round 10
// speedup vs baseline: 2.1411x; 1.2549x over previous
#include <cuda_runtime.h>
#include <cuda_fp16.h>
#include <cuda_bf16.h>
#include <math.h>

#define B_  4096
#define T_  256
#define E_  96
#define H_  6
#define HD_ 16
#define V_  98
#define EP  100     // padded row stride (halves) for Ek/Ev/Pk/Pv tables
#define GO  384     // stage-1 fused outputs: [r|z (192) | i_n (96) | h_n (96)]
#define S2O 224     // stage-2 padded outputs: [cand(96) | p(1) | head(98) | pad]
#define BB  8       // batch rows per block in K2
#define RB  16      // batch rows per block in K3
#define XP  20      // padded row stride (floats) for XsT (16 rows + 4 pad, f4-aligned)
#define OP  17      // padded row stride (floats) for Os

#define K2_SMEM_BYTES 111952
#define K3_SMEM_FLOATS (288*XP + GO*OP + 16 + 16 + 16)   // 5760+6528+48 = 12336

// -------- persistent scratch (__device__ globals; no allocation allowed) --------
__device__ float g_Eq[V_*E_];
__device__ __align__(16) __half g_Ek[V_*EP];
__device__ __align__(16) __half g_Ev[V_*EP];
__device__ __align__(16) __half g_Pk[T_*EP];
__device__ __align__(16) __half g_Pv[T_*EP];
__device__ float g_pq[E_];
__device__ float g_Gbig[V_*GO];     // per-vocab token contribution + all bias constants
__device__ float g_Wbig[288*GO];    // fused GRU weights; input X = [ctx_raw|memory|hidden]
__device__ float g_W2[E_*S2O];      // fused stage-2 weights [mw^T | pg | (ln_g*head)^T | pad]
__device__ float g_hg[V_];          // sum_e ln_g[e]*head_w[v][e]
__device__ float g_hc1[V_];         // sum_e ln_b[e]*head_w[v][e] + head_b[v]
__device__ float g_ctx[B_*E_];      // raw (pre-out_proj) attention context

__device__ __forceinline__ float dot4(float4 a, float4 b, float s){
    s = fmaf(a.x, b.x, s); s = fmaf(a.y, b.y, s);
    s = fmaf(a.z, b.z, s); s = fmaf(a.w, b.w, s);
    return s;
}
__device__ __forceinline__ float2 h2f(unsigned int u){
    return __half22float2(*reinterpret_cast<const __half2*>(&u));
}
// packed fp32x2 FMA (Blackwell): d = a*b + d, bit-exact IEEE fp32 per lane half
#define FMA2(d,a,b) asm("fma.rn.f32x2 %0, %1, %2, %0;" : "+l"(d) : "l"(a), "l"(b))

// cooperative 96-dot: 8 lanes, each reads 3 contiguous float4 of each row
__device__ __forceinline__ float gdot96(const float* a, const float* b,
                                        int l, unsigned gmask){
    const float4* a4 = (const float4*)a;
    const float4* b4 = (const float4*)b;
    float s = dot4(a4[l],    b4[l],    0.f);
    s       = dot4(a4[l+8],  b4[l+8],  s);
    s       = dot4(a4[l+16], b4[l+16], s);
    s += __shfl_xor_sync(gmask, s, 4);
    s += __shfl_xor_sync(gmask, s, 2);
    s += __shfl_xor_sync(gmask, s, 1);
    return s;
}

// ================= K1a: precompute, dot jobs (8 lanes / output) =================
#define N_EQ   (V_*E_)
#define N_EK   (V_*E_)
#define N_EV   (V_*E_)
#define N_PK   (T_*E_)
#define N_PV   (T_*E_)
#define N_PQ   (E_)
#define N_GB   (V_*288)
#define N_WA   (E_*288)
#define N_HG   (V_)
#define N_HC   (V_)
#define K1A_GROUPS (N_EQ+N_EK+N_EV+N_PK+N_PV+N_PQ+N_GB+N_WA+N_HG+N_HC)

__global__ void k1a_dots(
    const float* __restrict__ tok,  const float* __restrict__ pos,
    const float* __restrict__ ipw,  const float* __restrict__ ipb,
    const float* __restrict__ opw,  const float* __restrict__ opb,
    const float* __restrict__ gih,  const float* __restrict__ gbih,
    const float* __restrict__ gbhh, const float* __restrict__ lng,
    const float* __restrict__ lnb,  const float* __restrict__ headw,
    const float* __restrict__ headb)
{
    int g = (blockIdx.x*blockDim.x + threadIdx.x) >> 3;
    if (g >= K1A_GROUPS) return;
    const int l = threadIdx.x & 7;
    const unsigned gmask = 0xFFu << (threadIdx.x & 24);

    if (g < N_EQ){
        int v=g/E_, e=g%E_;
        float s = gdot96(tok+v*E_, ipw+e*E_, l, gmask);
        if (!l) g_Eq[v*E_+e] = s;
        return;
    }
    g -= N_EQ;
    if (g < N_EK){
        int v=g/E_, e=g%E_;
        float s = gdot96(tok+v*E_, ipw+(E_+e)*E_, l, gmask);
        if (!l) g_Ek[v*EP+e] = __float2half(s);
        return;
    }
    g -= N_EK;
    if (g < N_EV){
        int v=g/E_, e=g%E_;
        float s = gdot96(tok+v*E_, ipw+(2*E_+e)*E_, l, gmask);
        if (!l) g_Ev[v*EP+e] = __float2half(s);
        return;
    }
    g -= N_EV;
    if (g < N_PK){
        int t=g/E_, e=g%E_;
        float s = gdot96(pos+t*E_, ipw+(E_+e)*E_, l, gmask);
        if (!l) g_Pk[t*EP+e] = __float2half(s + ipb[E_+e]);
        return;
    }
    g -= N_PK;
    if (g < N_PV){
        int t=g/E_, e=g%E_;
        float s = gdot96(pos+t*E_, ipw+(2*E_+e)*E_, l, gmask);
        if (!l) g_Pv[t*EP+e] = __float2half(s + ipb[2*E_+e]);
        return;
    }
    g -= N_PV;
    if (g < N_PQ){
        int e=g;
        float s = gdot96(pos+(T_-1)*E_, ipw+e*E_, l, gmask);
        if (!l) g_pq[e] = s + ipb[e];
        return;
    }
    g -= N_PQ;
    if (g < N_GB){
        int v=g/288, o=g%288;
        float s = gdot96(tok+v*E_, gih+o*288, l, gmask)
                + gdot96(opb,      gih+o*288+E_, l, gmask);
        if (!l){
            s += gbih[o];
            if (o < 192) s += gbhh[o];
            g_Gbig[v*GO+o] = s;
        }
        return;
    }
    g -= N_GB;
    if (g < N_WA){
        int k=g/288, o=g%288;
        const float* gr = gih + o*288 + E_;
        float s = 0.f;
#pragma unroll
        for (int st=0; st<12; st++){
            int j = l + 8*st;
            s = fmaf(gr[j], opw[j*E_+k], s);
        }
        s += __shfl_xor_sync(gmask, s, 4);
        s += __shfl_xor_sync(gmask, s, 2);
        s += __shfl_xor_sync(gmask, s, 1);
        if (!l) g_Wbig[k*GO+o] = s;
        return;
    }
    g -= N_WA;
    if (g < N_HG){
        float s = gdot96(lng, headw+g*E_, l, gmask);
        if (!l) g_hg[g] = s;
        return;
    }
    g -= N_HG;
    {
        float s = gdot96(lnb, headw+g*E_, l, gmask);
        if (!l) g_hc1[g] = s + headb[g];
    }
}

// ================= K1b: precompute, copies / zeros (1 thread / elem) =============
#define K1B_TOTAL (V_*E_ + E_*E_ + 192*GO + E_*S2O)

__global__ void k1b_copies(
    const float* __restrict__ gih,  const float* __restrict__ ghh,
    const float* __restrict__ gbhh, const float* __restrict__ pgw,
    const float* __restrict__ mww,  const float* __restrict__ lng,
    const float* __restrict__ headw)
{
    int i = blockIdx.x*blockDim.x + threadIdx.x;
    if (i < V_*E_){
        int v=i/E_, n=i%E_;
        g_Gbig[v*GO + 288 + n] = gbhh[192+n];
        return;
    }
    i -= V_*E_;
    if (i < E_*E_){
        int k=i/E_, o=288 + i%E_;
        g_Wbig[k*GO+o] = 0.f;
        return;
    }
    i -= E_*E_;
    if (i < 192*GO){
        int k = 96 + i/GO, o = i%GO;
        float s = 0.f;
        if (k < 192){
            int m = k - 96;
            if (o < 288) s = gih[o*288 + 2*E_ + m];
        } else {
            int hh = k - 192;
            if (o < 192)       s = ghh[o*E_+hh];
            else if (o >= 288) s = ghh[(192+(o-288))*E_+hh];
        }
        g_Wbig[k*GO+o] = s;
        return;
    }
    i -= 192*GO;
    if (i < E_*S2O){
        int e=i/S2O, o=i%S2O; float s=0.f;
        if (o < 96)       s = mww[o*E_+e];
        else if (o == 96) s = pgw[e];
        else if (o < 195) s = headw[(o-97)*E_+e]*lng[e];
        g_W2[e*S2O+o] = s;
    }
}

// ================================ K2: attention ================================
__global__ __launch_bounds__(256, 2) void k2_attn(const int* __restrict__ hist)
{
    extern __shared__ char smc[];
    __half* Ek_s = (__half*)smc;                            // 9800 halves
    __half* Pk_s = (__half*)(smc + 19600);                  // 25600 halves
    float*  qh_s = (float*)(smc + 70800);                   // 768 floats
    __half* a_s  = (__half*)(smc + 73872);                  // 12288 halves
    unsigned short* idx_s = (unsigned short*)(smc + 98448); // 2048 u16
    __half* SE_s = (__half*)(smc + 102544);                 // 48*98 = 4704 halves

    const int tid = threadIdx.x;
    const int b0  = blockIdx.x * BB;

    for (int i = tid; i < BB*T_; i += 256)
        idx_s[i] = (unsigned short)hist[(b0 + (i>>8))*T_ + (i&255)];
    {
        const uint4* s4 = (const uint4*)g_Ek; uint4* d4 = (uint4*)Ek_s;
        for (int i = tid; i < (V_*EP)/8; i += 256) d4[i] = s4[i];
        const uint4* s5 = (const uint4*)g_Pk; uint4* d5 = (uint4*)Pk_s;
        for (int i = tid; i < (T_*EP)/8; i += 256) d5[i] = s5[i];
    }
    __syncthreads();

    for (int i = tid; i < BB*E_; i += 256) {
        int r = i / E_, e = i % E_;
        int li = idx_s[r*T_ + (T_-1)];
        qh_s[i] = g_Eq[li*E_+e] + g_pq[e];
    }
    __syncthreads();

    // SE phase: SE[r,h,v] = 0.25 * q[r,h] · Ek[v]
    for (int i = tid; i < H_*V_; i += 256){
        int h = i / V_, v = i % V_;
        const uint2* e2 = (const uint2*)(Ek_s + v*EP + h*HD_);
        uint2 u0=e2[0],u1=e2[1],u2=e2[2],u3=e2[3];
        float2 e0=h2f(u0.x),e1=h2f(u0.y),e2f_=h2f(u1.x),e3=h2f(u1.y);
        float2 e4=h2f(u2.x),e5=h2f(u2.y),e6=h2f(u3.x),e7=h2f(u3.y);
#pragma unroll
        for (int r=0;r<BB;r++){
            const float4* q4 = (const float4*)(qh_s + r*E_ + h*HD_);
            float4 q0=q4[0],q1=q4[1],q2=q4[2],q3=q4[3];
            float s =
              q0.x*e0.x+q0.y*e0.y+q0.z*e1.x+q0.w*e1.y
            + q1.x*e2f_.x+q1.y*e2f_.y+q1.z*e3.x+q1.w*e3.y
            + q2.x*e4.x+q2.y*e4.y+q2.z*e5.x+q2.w*e5.y
            + q3.x*e6.x+q3.y*e6.y+q3.z*e7.x+q3.w*e7.y;
            SE_s[(r*H_+h)*V_ + v] = __float2half(s * 0.25f);
        }
    }
    __syncthreads();

    {   // score phase
        const int t = tid;
        int myidx[BB];
#pragma unroll
        for (int r=0;r<BB;r++) myidx[r] = idx_s[r*T_+t];
#pragma unroll
        for (int h=0;h<H_;h++){
            const uint2* pk2 = (const uint2*)(Pk_s + t*EP + h*HD_);
            uint2 pu0=pk2[0], pu1=pk2[1], pu2=pk2[2], pu3=pk2[3];
            float2 p0=h2f(pu0.x),p1=h2f(pu0.y),p2=h2f(pu1.x),p3=h2f(pu1.y);
            float2 p4=h2f(pu2.x),p5=h2f(pu2.y),p6=h2f(pu3.x),p7=h2f(pu3.y);
#pragma unroll
            for (int r=0;r<BB;r++){
                const float4* q4 = (const float4*)(qh_s + r*E_ + h*HD_);
                float4 q0=q4[0],q1=q4[1],q2=q4[2],q3=q4[3];
                float d =
                  q0.x*p0.x+q0.y*p0.y+q0.z*p1.x+q0.w*p1.y
                + q1.x*p2.x+q1.y*p2.y+q1.z*p3.x+q1.w*p3.y
                + q2.x*p4.x+q2.y*p4.y+q2.z*p5.x+q2.w*p5.y
                + q3.x*p6.x+q3.y*p6.y+q3.z*p7.x+q3.w*p7.y;
                float se = __half2float(SE_s[(r*H_+h)*V_ + myidx[r]]);
                a_s[(r*H_+h)*T_ + t] = __float2half(fmaf(d, 0.25f, se));
            }
        }
    }
    __syncthreads();

    {   // swap tables to Ev/Pv + warp-per-row softmax
        const uint4* s4 = (const uint4*)g_Ev; uint4* d4 = (uint4*)Ek_s;
        for (int i = tid; i < (V_*EP)/8; i += 256) d4[i] = s4[i];
        const uint4* s5 = (const uint4*)g_Pv; uint4* d5 = (uint4*)Pk_s;
        for (int i = tid; i < (T_*EP)/8; i += 256) d5[i] = s5[i];

        int wid = tid>>5, lane = tid&31;
        int r = wid;
#pragma unroll
        for (int h=0;h<H_;h++){
            __half* row = a_s + (r*H_+h)*T_;
            float v[8]; float m = -1e30f;
#pragma unroll
            for (int j=0;j<8;j++){ v[j]=__half2float(row[lane+32*j]); m = fmaxf(m, v[j]); }
#pragma unroll
            for (int o=16;o;o>>=1) m = fmaxf(m, __shfl_xor_sync(0xffffffffu, m, o));
            float ssum = 0.f;
#pragma unroll
            for (int j=0;j<8;j++){ v[j]=__expf(v[j]-m); ssum += v[j]; }
#pragma unroll
            for (int o=16;o;o>>=1) ssum += __shfl_xor_sync(0xffffffffu, ssum, o);
            float inv = 1.f/ssum;
#pragma unroll
            for (int j=0;j<8;j++) row[lane+32*j] = __float2half(v[j]*inv);
        }
    }
    __syncthreads();

    if (tid < BB*24) {                      // ctx: thread = (row, 4-wide col group)
        int r = tid/24, g = tid%24;
        int h = g>>2, col = g*4;
        const __half* arow = a_s + (r*H_+h)*T_;
        const unsigned short* irow = idx_s + r*T_;
        float ax=0.f, ay=0.f, az=0.f, aw=0.f;
#pragma unroll 4
        for (int t2=0;t2<T_;t2++){
            float av = __half2float(arow[t2]);
            int   ix = irow[t2];
            uint2 eu = *(const uint2*)(Ek_s + ix*EP + col);   // holds Ev now
            uint2 pu = *(const uint2*)(Pk_s + t2*EP + col);   // holds Pv now
            float2 e0=h2f(eu.x), e1=h2f(eu.y), p0=h2f(pu.x), p1=h2f(pu.y);
            ax += av*(e0.x+p0.x); ay += av*(e0.y+p0.y);
            az += av*(e1.x+p1.x); aw += av*(e1.y+p1.y);
        }
        *(float4*)(g_ctx + (b0+r)*E_ + col) = make_float4(ax,ay,az,aw);
    }
}

// ==================== K3: fused GRU + memory gate + LN + head ====================
// RB=16 rows/block -> grid 256, smem 49.3 KB -> 2 CTAs/SM (16 warps) for latency
// hiding; inner loop batches all row loads (4x LDS.128) before the 8 FMA2s.
__constant__ signed char c_tmap[8][2] = {  // balanced warp->tile map (k-iters <= 384)
    {0,-1},{1,-1},{2,-1},{3,-1},{4,9},{5,10},{6,8},{7,11}
};

__global__ __launch_bounds__(256, 2) void k3_gru(
    const int* __restrict__ cidx, const float* __restrict__ hidden,
    const float* __restrict__ memory, const float* __restrict__ mwb,
    const float* __restrict__ pgb,
    float* __restrict__ out_logits, float* __restrict__ out_hidden,
    float* __restrict__ out_memory)
{
    extern __shared__ float sm[];
    float* XsT   = sm;                      // 288*XP = 5760 (k-major, 20-row pad)
    float* Os    = sm + 288*XP;             // 384*OP = 6528
    float* mu_s  = sm + 288*XP + GO*OP;     // 16
    float* rs_s  = mu_s + 16;               // 16
    int*   cidx_s= (int*)(rs_s + 16);       // 16

    const int tid = threadIdx.x;
    const int b0  = blockIdx.x * RB;
    const int wid = tid>>5, lane = tid&31;

    if (tid < RB) cidx_s[tid] = cidx[b0+tid];
    for (int i = tid; i < RB*E_; i += 256){
        int r = i/E_, c = i%E_;
        XsT[c*XP + r]        = g_ctx[(b0+r)*E_ + c];
        XsT[(E_+c)*XP + r]   = memory[(b0+r)*E_ + c];
        XsT[(2*E_+c)*XP + r] = hidden[(b0+r)*E_ + c];
    }
    __syncthreads();

    // stage-1 fused GEMM: Os[o][r] = sum_k X[r][k]*Wbig[k][o] + Gbig[cidx[r]][o]
#pragma unroll
    for (int ti = 0; ti < 2; ti++){
        int tile = c_tmap[wid][ti];
        if (tile < 0) continue;
        int o  = tile*32 + lane;
        int k0 = (tile >= 9) ? 192 : 0;
        int k1 = (tile < 6)  ? 288 : ((tile < 9) ? 192 : 288);
        unsigned long long acc2[8];
#pragma unroll
        for (int j=0;j<8;j++) acc2[j]=0ull;
#pragma unroll 8
        for (int k=k0;k<k1;k++){
            float wv = g_Wbig[k*GO + o];
            unsigned long long wv2;
            asm("mov.b64 %0, {%1, %1};" : "=l"(wv2) : "f"(wv));
            const ulonglong2* xr = (const ulonglong2*)(XsT + k*XP);
            ulonglong2 x0 = xr[0], x1 = xr[1], x2 = xr[2], x3 = xr[3];
            FMA2(acc2[0], x0.x, wv2); FMA2(acc2[1], x0.y, wv2);
            FMA2(acc2[2], x1.x, wv2); FMA2(acc2[3], x1.y, wv2);
            FMA2(acc2[4], x2.x, wv2); FMA2(acc2[5], x2.y, wv2);
            FMA2(acc2[6], x3.x, wv2); FMA2(acc2[7], x3.y, wv2);
        }
        const float* gb = g_Gbig;
#pragma unroll
        for (int j=0;j<8;j++){
            float lo, hi;
            asm("mov.b64 {%0, %1}, %2;" : "=f"(lo), "=f"(hi) : "l"(acc2[j]));
            int r0 = 2*j, r1 = 2*j+1;
            Os[o*OP + r0] = lo + gb[cidx_s[r0]*GO + o];
            Os[o*OP + r1] = hi + gb[cidx_s[r1]*GO + o];
        }
    }
    __syncthreads();

    // GRU elementwise -> new_hidden; stash nh^T in XsT[0:96)
    for (int i = tid; i < RB*E_; i += 256){
        int r = i/E_, e = i%E_;
        float orv = Os[e*OP+r];
        float ozv = Os[(E_+e)*OP+r];
        float oin = Os[(2*E_+e)*OP+r];
        float ohn = Os[(3*E_+e)*OP+r];
        float rr = 1.f/(1.f+__expf(-orv));
        float zz = 1.f/(1.f+__expf(-ozv));
        float nn = tanhf(oin + rr*ohn);
        float hp = XsT[(2*E_+e)*XP + r];
        float nh = (1.f-zz)*nn + zz*hp;
        XsT[e*XP + r] = nh;
        out_hidden[(b0+r)*E_ + e] = nh;
    }
    __syncthreads();

    // per-row mean / rstd (16 threads per row)
    {
        int r = tid>>4, l16 = tid&15;
        float s=0.f, sq=0.f;
#pragma unroll
        for (int e=l16; e<E_; e+=16){ float v = XsT[e*XP+r]; s += v; sq += v*v; }
#pragma unroll
        for (int o=8;o;o>>=1){
            s  += __shfl_xor_sync(0xffffffffu, s,  o);
            sq += __shfl_xor_sync(0xffffffffu, sq, o);
        }
        if (l16==0){
            float mu = s*(1.f/E_);
            float var = sq*(1.f/E_) - mu*mu;
            mu_s[r] = mu;
            rs_s[r] = rsqrtf(var + 1e-5f);
        }
    }
    __syncthreads();

    // stage-2 GEMM: Os[o][r] = sum_e nh[r][e]*W2[e][o]
    if (wid < 7){
        int o = wid*32 + lane;
        unsigned long long acc2[8];
#pragma unroll
        for (int j=0;j<8;j++) acc2[j]=0ull;
#pragma unroll 8
        for (int k=0;k<E_;k++){
            float wv = g_W2[k*S2O + o];
            unsigned long long wv2;
            asm("mov.b64 %0, {%1, %1};" : "=l"(wv2) : "f"(wv));
            const ulonglong2* xr = (const ulonglong2*)(XsT + k*XP);
            ulonglong2 x0 = xr[0], x1 = xr[1], x2 = xr[2], x3 = xr[3];
            FMA2(acc2[0], x0.x, wv2); FMA2(acc2[1], x0.y, wv2);
            FMA2(acc2[2], x1.x, wv2); FMA2(acc2[3], x1.y, wv2);
            FMA2(acc2[4], x2.x, wv2); FMA2(acc2[5], x2.y, wv2);
            FMA2(acc2[6], x3.x, wv2); FMA2(acc2[7], x3.y, wv2);
        }
#pragma unroll
        for (int j=0;j<8;j++){
            float lo, hi;
            asm("mov.b64 {%0, %1}, %2;" : "=f"(lo), "=f"(hi) : "l"(acc2[j]));
            Os[o*OP + 2*j]   = lo;
            Os[o*OP + 2*j+1] = hi;
        }
    }
    __syncthreads();

    // epilogue: memory gate
    float pgb0 = pgb[0];
    for (int i = tid; i < RB*E_; i += 256){
        int r = i/E_, e = i%E_;
        float p    = 1.f/(1.f+__expf(-(Os[96*OP+r] + pgb0)));
        float cand = tanhf(Os[e*OP+r] + mwb[e]);
        float mem  = XsT[(E_+e)*XP + r];
        out_memory[(b0+r)*E_ + e] = (1.f-p)*mem + p*cand;
    }
    // epilogue: logits via folded LN+head
    for (int i = tid; i < RB*V_; i += 256){
        int r = i/V_, v = i%V_;
        float y = Os[(97+v)*OP + r];
        out_logits[(b0+r)*V_ + v] = rs_s[r]*(y - mu_s[r]*g_hg[v]) + g_hc1[v];
    }
}

// ================================== launch ==================================
extern "C" void kernel_launch(void* const* d_in, const int* in_sizes, int n_in,
                              void* d_out, int out_size)
{
    const int*   cidx = (const int*)  d_in[0];
    const int*   hist = (const int*)  d_in[1];
    const float* hid  = (const float*)d_in[2];
    const float* mem  = (const float*)d_in[3];
    const float* tok  = (const float*)d_in[4];
    const float* pos  = (const float*)d_in[5];
    const float* ipw  = (const float*)d_in[6];
    const float* ipb  = (const float*)d_in[7];
    const float* opw  = (const float*)d_in[8];
    const float* opb  = (const float*)d_in[9];
    const float* gih  = (const float*)d_in[10];
    const float* ghh  = (const float*)d_in[11];
    const float* gbih = (const float*)d_in[12];
    const float* gbhh = (const float*)d_in[13];
    const float* pgw  = (const float*)d_in[14];
    const float* pgb  = (const float*)d_in[15];
    const float* mww  = (const float*)d_in[16];
    const float* mwb  = (const float*)d_in[17];
    const float* lng  = (const float*)d_in[18];
    const float* lnb  = (const float*)d_in[19];
    const float* hdw  = (const float*)d_in[20];
    const float* hdb  = (const float*)d_in[21];

    float* out         = (float*)d_out;
    float* out_logits  = out;
    float* out_hidden  = out + (size_t)B_*V_;
    float* out_memory  = out + (size_t)B_*V_ + (size_t)B_*E_;

    cudaFuncSetAttribute(k2_attn, cudaFuncAttributeMaxDynamicSharedMemorySize,
                         K2_SMEM_BYTES);
    cudaFuncSetAttribute(k3_gru,  cudaFuncAttributeMaxDynamicSharedMemorySize,
                         K3_SMEM_FLOATS*4);

    const int k1a_blocks = (K1A_GROUPS*8 + 255) / 256;
    const int k1b_blocks = (K1B_TOTAL   + 255) / 256;
    k1a_dots<<<k1a_blocks, 256>>>(tok,pos,ipw,ipb,opw,opb,
                                  gih,gbih,gbhh,lng,lnb,hdw,hdb);
    k1b_copies<<<k1b_blocks, 256>>>(gih,ghh,gbhh,pgw,mww,lng,hdw);
    k2_attn<<<B_/BB, 256, K2_SMEM_BYTES>>>(hist);
    k3_gru <<<B_/RB, 256, K3_SMEM_FLOATS*4>>>(cidx, hid, mem, mwb, pgb,
                                              out_logits, out_hidden, out_memory);
}